// round 6
// baseline (speedup 1.0000x reference)
#include <cuda_runtime.h>
#include <cuda_bf16.h>

// Shapes (compile-time constants)
#define NB   512           // sequence length
#define DD   256           // model dim
#define HH   8             // heads
#define HID  682           // swiglu hidden
#define QKVD 768

typedef unsigned long long u64;

// ---------------- device scratch ----------------
__device__ float g_xn[NB * DD];
__device__ float g_qkv[NB * QKVD];
__device__ float2 g_PKT[DD * NB];    // (.x = K^T[k][j], .y = Pb^T[k][j])
__device__ float g_Pb[NB * DD];
__device__ float g_Pv[NB * DD];
__device__ float g_rv2T[DD * DD];    // rv2 transposed [k][d]
__device__ float g_w[NB * NB * HH];  // softmax weights [i][j*HH+h]  (8MB)
__device__ float g_y[NB * DD];
__device__ float g_xn2[NB * DD];
__device__ float g_h1[NB * HID];

// ---- packed f32x2 helpers (sm_100+) ----
__device__ __forceinline__ u64 pk2(float lo, float hi) {
    u64 r;
    asm("mov.b64 %0, {%1, %2};" : "=l"(r) : "f"(lo), "f"(hi));
    return r;
}
__device__ __forceinline__ float2 up2(u64 v) {
    float2 f;
    asm("mov.b64 {%0, %1}, %2;" : "=f"(f.x), "=f"(f.y) : "l"(v));
    return f;
}
__device__ __forceinline__ u64 fma2(u64 a, u64 b, u64 c) {
    u64 d;
    asm("fma.rn.f32x2 %0, %1, %2, %3;" : "=l"(d) : "l"(a), "l"(b), "l"(c));
    return d;
}
__device__ __forceinline__ u64 add2(u64 a, u64 b) {
    u64 d;
    asm("add.rn.f32x2 %0, %1, %2;" : "=l"(d) : "l"(a), "l"(b));
    return d;
}

// fast silu via MUFU.TANH: v * (0.5*tanh(v/2) + 0.5)  -- 1 MUFU
__device__ __forceinline__ float silu_f(float v) {
    float t;
    asm("tanh.approx.f32 %0, %1;" : "=f"(t) : "f"(v * 0.5f));
    return v * fmaf(t, 0.5f, 0.5f);
}
// accurate silu for the (cold) FFN epilogue
__device__ __forceinline__ float silu_acc(float v) {
    return v / (1.0f + __expf(-v));
}

// ---------------- LayerNorm: one block per row, 256 threads ----------------
__global__ __launch_bounds__(256) void ln_kernel(const float* __restrict__ x,
                                                 const float* __restrict__ w,
                                                 const float* __restrict__ b,
                                                 float* __restrict__ out) {
    int row = blockIdx.x, t = threadIdx.x;
    float v = x[row * DD + t];
    float s = v, q = v * v;
#pragma unroll
    for (int o = 16; o; o >>= 1) {
        s += __shfl_xor_sync(0xffffffff, s, o);
        q += __shfl_xor_sync(0xffffffff, q, o);
    }
    __shared__ float ss[8], sq[8];
    int warp = t >> 5, lane = t & 31;
    if (lane == 0) { ss[warp] = s; sq[warp] = q; }
    __syncthreads();
    s = 0.f; q = 0.f;
#pragma unroll
    for (int k = 0; k < 8; k++) { s += ss[k]; q += sq[k]; }
    float mean = s * (1.0f / DD);
    float var = q * (1.0f / DD) - mean * mean;
    out[row * DD + t] = (v - mean) * rsqrtf(var + 1e-5f) * w[t] + b[t];
}

// ---------------- coords projection ----------------
__global__ __launch_bounds__(256) void proj3_kernel(const float* __restrict__ coords,
                                                    const float* __restrict__ rb1,
                                                    const float* __restrict__ rv1,
                                                    float* __restrict__ Pb,
                                                    float2* __restrict__ PKT,
                                                    float* __restrict__ Pv) {
    int i = blockIdx.x, k = threadIdx.x;
    float c0 = coords[i * 3 + 0], c1 = coords[i * 3 + 1], c2 = coords[i * 3 + 2];
    float pb = rb1[k * 3 + 0] * c0 + rb1[k * 3 + 1] * c1 + rb1[k * 3 + 2] * c2;
    float pv = rv1[k * 3 + 0] * c0 + rv1[k * 3 + 1] * c1 + rv1[k * 3 + 2] * c2;
    Pb[i * DD + k] = pb;
    PKT[k * NB + i].y = pb;
    Pv[i * DD + k] = pv;
}

// ---------------- K^T pack: PKT[k][j].x = qkv[j][DD + k] ----------------
__global__ __launch_bounds__(256) void kt_pack_kernel(const float* __restrict__ qkv,
                                                      float2* __restrict__ PKT) {
    __shared__ float tile[32][33];
    int c0 = blockIdx.x * 32, r0 = blockIdx.y * 32;   // c = k dim, r = j dim
    int tx = threadIdx.x, ty = threadIdx.y;  // 32 x 8
#pragma unroll
    for (int s = 0; s < 32; s += 8)
        tile[ty + s][tx] = qkv[(r0 + ty + s) * QKVD + DD + c0 + tx];
    __syncthreads();
#pragma unroll
    for (int s = 0; s < 32; s += 8)
        PKT[(c0 + ty + s) * NB + r0 + tx].x = tile[tx][ty + s];
}

// ---------------- generic 32x32-tiled transpose ----------------
__global__ __launch_bounds__(256) void transpose_kernel(const float* __restrict__ in,
                                                        float* __restrict__ out,
                                                        int R, int C, int ldin, int off) {
    __shared__ float tile[32][33];
    int c0 = blockIdx.x * 32, r0 = blockIdx.y * 32;
    int tx = threadIdx.x, ty = threadIdx.y;  // 32 x 8
#pragma unroll
    for (int s = 0; s < 32; s += 8)
        tile[ty + s][tx] = in[(r0 + ty + s) * ldin + off + c0 + tx];
    __syncthreads();
#pragma unroll
    for (int s = 0; s < 32; s += 8)
        out[(c0 + ty + s) * R + r0 + tx] = tile[tx][ty + s];
}

// ---------------- GEMM: C = A @ W^T (+bias)(+residual), 32x64 tile ----------------
__global__ __launch_bounds__(256, 2) void gemm_t(const float* __restrict__ A,
                                                 const float* __restrict__ W,
                                                 const float* __restrict__ bias,
                                                 const float* __restrict__ residual,
                                                 float* __restrict__ C,
                                                 int M, int N, int K) {
    __shared__ __align__(16) u64 As[32][34];     // [k][m] duplicated
    __shared__ __align__(16) float Ws[32][68];   // [k][n]
    int tid = threadIdx.x;
    int tx = tid & 15, ty = tid >> 4;            // tx -> n (4 cols), ty -> m (2 rows)
    int row0 = blockIdx.y * 32, col0 = blockIdx.x * 64;
    u64 acc[2][2] = {};
    for (int k0 = 0; k0 < K; k0 += 32) {
#pragma unroll
        for (int l = 0; l < 4; l++) {            // A: 32x32
            int idx = l * 256 + tid;
            int m = idx >> 5, k = idx & 31;
            int gk = k0 + k, ar = row0 + m;
            float v = (ar < M && gk < K) ? A[ar * K + gk] : 0.f;
            As[k][m] = pk2(v, v);
        }
#pragma unroll
        for (int l = 0; l < 8; l++) {            // W: 64x32
            int idx = l * 256 + tid;
            int m = idx >> 5, k = idx & 31;
            int gk = k0 + k, wr = col0 + m;
            Ws[k][m] = (wr < N && gk < K) ? W[wr * K + gk] : 0.f;
        }
        __syncthreads();
#pragma unroll
        for (int kk = 0; kk < 32; kk++) {
            ulonglong2 Av = *(const ulonglong2*)&As[kk][ty * 2];
            ulonglong2 Bv = *(const ulonglong2*)&Ws[kk][tx * 4];
            acc[0][0] = fma2(Av.x, Bv.x, acc[0][0]);
            acc[0][1] = fma2(Av.x, Bv.y, acc[0][1]);
            acc[1][0] = fma2(Av.y, Bv.x, acc[1][0]);
            acc[1][1] = fma2(Av.y, Bv.y, acc[1][1]);
        }
        __syncthreads();
    }
#pragma unroll
    for (int r = 0; r < 2; r++) {
        int m = row0 + ty * 2 + r;
        if (m >= M) continue;
#pragma unroll
        for (int c2 = 0; c2 < 2; c2++) {
            float2 v = up2(acc[r][c2]);
            int n0 = col0 + tx * 4 + c2 * 2;
            if (n0 < N) {
                float o = v.x;
                if (bias) o += bias[n0];
                if (residual) o += residual[m * N + n0];
                C[m * N + n0] = o;
            }
            if (n0 + 1 < N) {
                float o = v.y;
                if (bias) o += bias[n0 + 1];
                if (residual) o += residual[m * N + n0 + 1];
                C[m * N + n0 + 1] = o;
            }
        }
    }
}

// ---------------- GEMM 32x32 tile (better grid fill for small N) ----------------
__global__ __launch_bounds__(256, 3) void gemm_t32(const float* __restrict__ A,
                                                   const float* __restrict__ W,
                                                   const float* __restrict__ bias,
                                                   const float* __restrict__ residual,
                                                   float* __restrict__ C,
                                                   int M, int N, int K) {
    __shared__ __align__(16) u64 As[32][34];     // [k][m] duplicated
    __shared__ __align__(16) float Ws[32][36];   // [k][n]
    int tid = threadIdx.x;
    int tx = tid & 7, ty = tid >> 3;             // tx -> n (4 cols), ty -> m (1 row)
    int row0 = blockIdx.y * 32, col0 = blockIdx.x * 32;
    u64 acc[2] = {};
    for (int k0 = 0; k0 < K; k0 += 32) {
#pragma unroll
        for (int l = 0; l < 4; l++) {
            int idx = l * 256 + tid;
            int m = idx >> 5, k = idx & 31;
            int gk = k0 + k;
            int ar = row0 + m, wr = col0 + m;
            float va = (ar < M && gk < K) ? A[ar * K + gk] : 0.f;
            As[k][m] = pk2(va, va);
            Ws[k][m] = (wr < N && gk < K) ? W[wr * K + gk] : 0.f;
        }
        __syncthreads();
#pragma unroll
        for (int kk = 0; kk < 32; kk++) {
            u64 Av = As[kk][ty];
            ulonglong2 Bv = *(const ulonglong2*)&Ws[kk][tx * 4];
            acc[0] = fma2(Av, Bv.x, acc[0]);
            acc[1] = fma2(Av, Bv.y, acc[1]);
        }
        __syncthreads();
    }
    int m = row0 + ty;
    if (m < M) {
#pragma unroll
        for (int c2 = 0; c2 < 2; c2++) {
            float2 v = up2(acc[c2]);
            int n0 = col0 + tx * 4 + c2 * 2;
            if (n0 < N) {
                float o = v.x;
                if (bias) o += bias[n0];
                if (residual) o += residual[m * N + n0];
                C[m * N + n0] = o;
            }
            if (n0 + 1 < N) {
                float o = v.y;
                if (bias) o += bias[n0 + 1];
                if (residual) o += residual[m * N + n0 + 1];
                C[m * N + n0 + 1] = o;
            }
        }
    }
}

// ---------------- fused SwiGLU dual-GEMM, 32x64 tile ----------------
__global__ __launch_bounds__(256, 2) void gemm_swiglu(const float* __restrict__ A,
                                                      const float* __restrict__ W1,
                                                      const float* __restrict__ b1,
                                                      const float* __restrict__ W2,
                                                      const float* __restrict__ b2,
                                                      float* __restrict__ Hout,
                                                      int M, int N, int K) {
    __shared__ __align__(16) u64 As[32][34];
    __shared__ __align__(16) float W1s[32][68];
    __shared__ __align__(16) float W2s[32][68];
    int tid = threadIdx.x;
    int tx = tid & 15, ty = tid >> 4;
    int row0 = blockIdx.y * 32, col0 = blockIdx.x * 64;
    u64 acc1[2][2] = {};
    u64 acc2[2][2] = {};
    for (int k0 = 0; k0 < K; k0 += 32) {
#pragma unroll
        for (int l = 0; l < 4; l++) {
            int idx = l * 256 + tid;
            int m = idx >> 5, k = idx & 31;
            int gk = k0 + k, ar = row0 + m;
            float v = (ar < M && gk < K) ? A[ar * K + gk] : 0.f;
            As[k][m] = pk2(v, v);
        }
#pragma unroll
        for (int l = 0; l < 8; l++) {
            int idx = l * 256 + tid;
            int m = idx >> 5, k = idx & 31;
            int gk = k0 + k, wr = col0 + m;
            W1s[k][m] = (wr < N && gk < K) ? W1[wr * K + gk] : 0.f;
            W2s[k][m] = (wr < N && gk < K) ? W2[wr * K + gk] : 0.f;
        }
        __syncthreads();
#pragma unroll
        for (int kk = 0; kk < 32; kk++) {
            ulonglong2 Av = *(const ulonglong2*)&As[kk][ty * 2];
            ulonglong2 Bv = *(const ulonglong2*)&W1s[kk][tx * 4];
            ulonglong2 Cv = *(const ulonglong2*)&W2s[kk][tx * 4];
            acc1[0][0] = fma2(Av.x, Bv.x, acc1[0][0]);
            acc1[0][1] = fma2(Av.x, Bv.y, acc1[0][1]);
            acc1[1][0] = fma2(Av.y, Bv.x, acc1[1][0]);
            acc1[1][1] = fma2(Av.y, Bv.y, acc1[1][1]);
            acc2[0][0] = fma2(Av.x, Cv.x, acc2[0][0]);
            acc2[0][1] = fma2(Av.x, Cv.y, acc2[0][1]);
            acc2[1][0] = fma2(Av.y, Cv.x, acc2[1][0]);
            acc2[1][1] = fma2(Av.y, Cv.y, acc2[1][1]);
        }
        __syncthreads();
    }
#pragma unroll
    for (int r = 0; r < 2; r++) {
        int m = row0 + ty * 2 + r;
        if (m >= M) continue;
#pragma unroll
        for (int c2 = 0; c2 < 2; c2++) {
            float2 v1 = up2(acc1[r][c2]);
            float2 v2 = up2(acc2[r][c2]);
            int n0 = col0 + tx * 4 + c2 * 2;
            if (n0 < N)
                Hout[m * N + n0] = silu_acc(v1.x + b1[n0]) * (v2.x + b2[n0]);
            if (n0 + 1 < N)
                Hout[m * N + n0 + 1] = silu_acc(v1.y + b1[n0 + 1]) * (v2.y + b2[n0 + 1]);
        }
    }
}

// ---------------- attention part 1: logits + softmax -> g_w ----------------
__global__ __launch_bounds__(256, 3) void attn_logits(
    const float* __restrict__ qkv, const float2* __restrict__ PKT,
    const float* __restrict__ Pb, const float* __restrict__ rb1_b,
    const float* __restrict__ rb2_w, const float* __restrict__ rb2_b,
    float* __restrict__ gw_all) {
    const int i0 = blockIdx.x * 2;
    const int t = threadIdx.x;

    __shared__ __align__(16) float2 sm_qpq[2][DD];     // (q[k], Pbq[k]) per query
    __shared__ __align__(16) float sm_rb2[DD * HH];    // rb2 transposed [k][h]
    __shared__ __align__(16) float sm_w[2][NB * HH];   // logits -> weights [q][j][h]

#pragma unroll
    for (int q = 0; q < 2; q++) {
        int iq = i0 + q;
        sm_qpq[q][t] = make_float2(qkv[iq * QKVD + t], Pb[iq * DD + t] + rb1_b[t]);
    }
#pragma unroll
    for (int h = 0; h < HH; h++) sm_rb2[t * HH + h] = rb2_w[h * DD + t];
    __syncthreads();

    // ---- Phase A: logits for (q in {0,1}) x (j0 = t, j1 = t+256) ----
    {
        const int j0 = t, j1 = t + 256;
        u64 bias[2][2][4] = {};   // [q][jslot][head pair]
        const float sc = 0.17677669529663687f;
#pragma unroll
        for (int h = 0; h < HH; h++) {
            u64 qk[2] = {0ull, 0ull};   // packed over (j0, j1)
#pragma unroll 4
            for (int kk = 0; kk < 32; kk++) {
                int k = h * 32 + kk;
                float2 pk0 = PKT[k * NB + j0];
                float2 pk1 = PKT[k * NB + j1];
                u64 kvp = pk2(pk0.x, pk1.x);
                ulonglong2 rA = *(const ulonglong2*)(sm_rb2 + k * HH);
                ulonglong2 rB = *(const ulonglong2*)(sm_rb2 + k * HH + 4);
#pragma unroll
                for (int q = 0; q < 2; q++) {
                    float2 qp = sm_qpq[q][k];
                    qk[q] = fma2(pk2(qp.x, qp.x), kvp, qk[q]);
                    float u0 = silu_f(qp.y - pk0.y);
                    float u1 = silu_f(qp.y - pk1.y);
                    u64 u0p = pk2(u0, u0);
                    u64 u1p = pk2(u1, u1);
                    bias[q][0][0] = fma2(u0p, rA.x, bias[q][0][0]);
                    bias[q][0][1] = fma2(u0p, rA.y, bias[q][0][1]);
                    bias[q][0][2] = fma2(u0p, rB.x, bias[q][0][2]);
                    bias[q][0][3] = fma2(u0p, rB.y, bias[q][0][3]);
                    bias[q][1][0] = fma2(u1p, rA.x, bias[q][1][0]);
                    bias[q][1][1] = fma2(u1p, rA.y, bias[q][1][1]);
                    bias[q][1][2] = fma2(u1p, rB.x, bias[q][1][2]);
                    bias[q][1][3] = fma2(u1p, rB.y, bias[q][1][3]);
                }
            }
            // fold qk*sc into bias pair c = h>>1, slot h&1
            int c = h >> 1;
#pragma unroll
            for (int q = 0; q < 2; q++) {
                float2 qv = up2(qk[q]);
                float s0 = qv.x * sc, s1 = qv.y * sc;
                u64 p0 = (h & 1) ? pk2(0.f, s0) : pk2(s0, 0.f);
                u64 p1 = (h & 1) ? pk2(0.f, s1) : pk2(s1, 0.f);
                bias[q][0][c] = add2(bias[q][0][c], p0);
                bias[q][1][c] = add2(bias[q][1][c], p1);
            }
        }
#pragma unroll
        for (int c = 0; c < 4; c++) {
            u64 bb = pk2(rb2_b[2 * c], rb2_b[2 * c + 1]);
            *(u64*)(&sm_w[0][j0 * HH + 2 * c]) = add2(bias[0][0][c], bb);
            *(u64*)(&sm_w[0][j1 * HH + 2 * c]) = add2(bias[0][1][c], bb);
            *(u64*)(&sm_w[1][j0 * HH + 2 * c]) = add2(bias[1][0][c], bb);
            *(u64*)(&sm_w[1][j1 * HH + 2 * c]) = add2(bias[1][1][c], bb);
        }
    }
    __syncthreads();

    // ---- softmax: warp h handles head h, loop over both queries ----
    {
        int h = t >> 5, lane = t & 31;
#pragma unroll
        for (int q = 0; q < 2; q++) {
            float* wq = sm_w[q];
            float m = -1e30f;
            for (int j = lane; j < NB; j += 32) m = fmaxf(m, wq[j * HH + h]);
#pragma unroll
            for (int o = 16; o; o >>= 1) m = fmaxf(m, __shfl_xor_sync(0xffffffff, m, o));
            float s = 0.f;
            for (int j = lane; j < NB; j += 32) {
                float e = __expf(wq[j * HH + h] - m);
                wq[j * HH + h] = e;
                s += e;
            }
#pragma unroll
            for (int o = 16; o; o >>= 1) s += __shfl_xor_sync(0xffffffff, s, o);
            float inv = 1.0f / s;
            for (int j = lane; j < NB; j += 32) wq[j * HH + h] *= inv;
        }
    }
    __syncthreads();

    // ---- bulk copy weights to gmem ----
    {
        float4* dst = (float4*)(gw_all + i0 * NB * HH);
        const float4* src = (const float4*)sm_w;
#pragma unroll
        for (int idx = t; idx < 2 * NB * HH / 4; idx += 256) dst[idx] = src[idx];
    }
}

// ---------------- attention part 2: T accumulation + context + output ---------------
// 4 queries per block
__global__ __launch_bounds__(256, 2) void attn_out(
    const float* __restrict__ x, const float* __restrict__ qkv,
    const float* __restrict__ Pv, const float* __restrict__ rv1_b,
    const float* __restrict__ rv2T, const float* __restrict__ rv2_b,
    const float* __restrict__ gw_all, float* __restrict__ y) {
    const int i0 = blockIdx.x * 4;
    const int t = threadIdx.x;

    __shared__ __align__(16) float sm_T[4][HH * DD];   // [q][h][k], 32KB

    const float* gw0 = gw_all + i0 * NB * HH;
    const float* gw1 = gw0 + NB * HH;
    const float* gw2 = gw1 + NB * HH;
    const float* gw3 = gw2 + NB * HH;

    // ---- Phase B: T[q][h,k], thread t owns k = t ----
    {
        float pvb = rv1_b[t];
        float pvq0 = Pv[(i0 + 0) * DD + t] + pvb;
        float pvq1 = Pv[(i0 + 1) * DD + t] + pvb;
        float pvq2 = Pv[(i0 + 2) * DD + t] + pvb;
        float pvq3 = Pv[(i0 + 3) * DD + t] + pvb;
        u64 T0[4] = {}, T1[4] = {}, T2[4] = {}, T3[4] = {};
#pragma unroll 2
        for (int j = 0; j < NB; j++) {
            float pv = Pv[j * DD + t];
            float s0 = silu_f(pvq0 - pv);
            float s1 = silu_f(pvq1 - pv);
            float s2 = silu_f(pvq2 - pv);
            float s3 = silu_f(pvq3 - pv);
            u64 s0p = pk2(s0, s0), s1p = pk2(s1, s1);
            u64 s2p = pk2(s2, s2), s3p = pk2(s3, s3);
            ulonglong2 wA0 = *(const ulonglong2*)(gw0 + j * HH);
            ulonglong2 wA1 = *(const ulonglong2*)(gw0 + j * HH + 4);
            ulonglong2 wB0 = *(const ulonglong2*)(gw1 + j * HH);
            ulonglong2 wB1 = *(const ulonglong2*)(gw1 + j * HH + 4);
            ulonglong2 wC0 = *(const ulonglong2*)(gw2 + j * HH);
            ulonglong2 wC1 = *(const ulonglong2*)(gw2 + j * HH + 4);
            ulonglong2 wD0 = *(const ulonglong2*)(gw3 + j * HH);
            ulonglong2 wD1 = *(const ulonglong2*)(gw3 + j * HH + 4);
            T0[0] = fma2(s0p, wA0.x, T0[0]); T0[1] = fma2(s0p, wA0.y, T0[1]);
            T0[2] = fma2(s0p, wA1.x, T0[2]); T0[3] = fma2(s0p, wA1.y, T0[3]);
            T1[0] = fma2(s1p, wB0.x, T1[0]); T1[1] = fma2(s1p, wB0.y, T1[1]);
            T1[2] = fma2(s1p, wB1.x, T1[2]); T1[3] = fma2(s1p, wB1.y, T1[3]);
            T2[0] = fma2(s2p, wC0.x, T2[0]); T2[1] = fma2(s2p, wC0.y, T2[1]);
            T2[2] = fma2(s2p, wC1.x, T2[2]); T2[3] = fma2(s2p, wC1.y, T2[3]);
            T3[0] = fma2(s3p, wD0.x, T3[0]); T3[1] = fma2(s3p, wD0.y, T3[1]);
            T3[2] = fma2(s3p, wD1.x, T3[2]); T3[3] = fma2(s3p, wD1.y, T3[3]);
        }
#pragma unroll
        for (int c = 0; c < 4; c++) {
            float2 a = up2(T0[c]);
            sm_T[0][(2 * c) * DD + t] = a.x;
            sm_T[0][(2 * c + 1) * DD + t] = a.y;
            float2 b = up2(T1[c]);
            sm_T[1][(2 * c) * DD + t] = b.x;
            sm_T[1][(2 * c + 1) * DD + t] = b.y;
            float2 cc = up2(T2[c]);
            sm_T[2][(2 * c) * DD + t] = cc.x;
            sm_T[2][(2 * c + 1) * DD + t] = cc.y;
            float2 d = up2(T3[c]);
            sm_T[3][(2 * c) * DD + t] = d.x;
            sm_T[3][(2 * c + 1) * DD + t] = d.y;
        }
    }
    __syncthreads();

    // ---- output: context1 + context2 + residual, for all 4 queries ----
    {
        const int d = t;
        const int h = d >> 5;
        float c1a = 0.f, c1b = 0.f, c1c = 0.f, c1d = 0.f;
        const float* V = qkv + 2 * DD;
#pragma unroll 4
        for (int j = 0; j < NB; j++) {
            float v = V[j * QKVD + d];
            c1a += gw0[j * HH + h] * v;
            c1b += gw1[j * HH + h] * v;
            c1c += gw2[j * HH + h] * v;
            c1d += gw3[j * HH + h] * v;
        }
        float bv = rv2_b[d];
        float c2a = bv, c2b = bv, c2c = bv, c2d = bv;
        const float* T0s = sm_T[0] + h * DD;
        const float* T1s = sm_T[1] + h * DD;
        const float* T2s = sm_T[2] + h * DD;
        const float* T3s = sm_T[3] + h * DD;
#pragma unroll 4
        for (int k = 0; k < DD; k++) {
            float rv = rv2T[k * DD + d];
            c2a += rv * T0s[k];
            c2b += rv * T1s[k];
            c2c += rv * T2s[k];
            c2d += rv * T3s[k];
        }
        y[(i0 + 0) * DD + d] = x[(i0 + 0) * DD + d] + c1a + c2a;
        y[(i0 + 1) * DD + d] = x[(i0 + 1) * DD + d] + c1b + c2b;
        y[(i0 + 2) * DD + d] = x[(i0 + 2) * DD + d] + c1c + c2c;
        y[(i0 + 3) * DD + d] = x[(i0 + 3) * DD + d] + c1d + c2d;
    }
}

// ---------------- host launcher ----------------
extern "C" void kernel_launch(void* const* d_in, const int* in_sizes, int n_in,
                              void* d_out, int out_size) {
    const float* x      = (const float*)d_in[0];
    const float* coords = (const float*)d_in[1];
    const float* ln1_w  = (const float*)d_in[2];
    const float* ln1_b  = (const float*)d_in[3];
    const float* ln2_w  = (const float*)d_in[4];
    const float* ln2_b  = (const float*)d_in[5];
    const float* qkv_w  = (const float*)d_in[6];
    const float* qkv_b  = (const float*)d_in[7];
    const float* rb1_w  = (const float*)d_in[8];
    const float* rb1_b  = (const float*)d_in[9];
    const float* rb2_w  = (const float*)d_in[10];
    const float* rb2_b  = (const float*)d_in[11];
    const float* rv1_w  = (const float*)d_in[12];
    const float* rv1_b  = (const float*)d_in[13];
    const float* rv2_w  = (const float*)d_in[14];
    const float* rv2_b  = (const float*)d_in[15];
    const float* ffn_w1 = (const float*)d_in[16];
    const float* ffn_b1 = (const float*)d_in[17];
    const float* ffn_w2 = (const float*)d_in[18];
    const float* ffn_b2 = (const float*)d_in[19];
    const float* ffn_w3 = (const float*)d_in[20];
    const float* ffn_b3 = (const float*)d_in[21];
    float* out = (float*)d_out;

    float *p_xn, *p_qkv, *p_Pb, *p_Pv, *p_rv2T, *p_w, *p_y, *p_xn2, *p_h1;
    float2* p_PKT;
    cudaGetSymbolAddress((void**)&p_xn, g_xn);
    cudaGetSymbolAddress((void**)&p_qkv, g_qkv);
    cudaGetSymbolAddress((void**)&p_PKT, g_PKT);
    cudaGetSymbolAddress((void**)&p_Pb, g_Pb);
    cudaGetSymbolAddress((void**)&p_Pv, g_Pv);
    cudaGetSymbolAddress((void**)&p_rv2T, g_rv2T);
    cudaGetSymbolAddress((void**)&p_w, g_w);
    cudaGetSymbolAddress((void**)&p_y, g_y);
    cudaGetSymbolAddress((void**)&p_xn2, g_xn2);
    cudaGetSymbolAddress((void**)&p_h1, g_h1);

    dim3 tthr(32, 8);

    // 1. LN1
    ln_kernel<<<NB, 256>>>(x, ln1_w, ln1_b, p_xn);
    // 2. QKV = xn @ qkv_w^T + qkv_b    [512,768]
    gemm_t<<<dim3(QKVD / 64, NB / 32), 256>>>(p_xn, qkv_w, qkv_b, nullptr, p_qkv,
                                              NB, QKVD, DD);
    // 3. coords projections (Pb, PKT.y, Pv)
    proj3_kernel<<<NB, 256>>>(coords, rb1_w, rv1_w, p_Pb, p_PKT, p_Pv);
    // 4. K^T pack into PKT.x, rv2^T
    kt_pack_kernel<<<dim3(DD / 32, NB / 32), tthr>>>(p_qkv, p_PKT);
    transpose_kernel<<<dim3(DD / 32, DD / 32), tthr>>>(rv2_w, p_rv2T, DD, DD, DD, 0);
    // 5. attention part 1: logits + softmax
    attn_logits<<<NB / 2, 256>>>(p_qkv, p_PKT, p_Pb, rb1_b, rb2_w, rb2_b, p_w);
    // 6. attention part 2: T + context + output (y = x + attn_out)
    attn_out<<<NB / 4, 256>>>(x, p_qkv, p_Pv, rv1_b, p_rv2T, rv2_b, p_w, p_y);
    // 7. LN2
    ln_kernel<<<NB, 256>>>(p_y, ln2_w, ln2_b, p_xn2);
    // 8. fused SwiGLU dual-GEMM
    gemm_swiglu<<<dim3((HID + 63) / 64, NB / 32), 256>>>(p_xn2, ffn_w1, ffn_b1,
                                                         ffn_w2, ffn_b2, p_h1,
                                                         NB, HID, DD);
    // 9. out = h1 @ ffn_w3^T + ffn_b3 + y   (32x32 tiles -> 128 blocks)
    gemm_t32<<<dim3(DD / 32, NB / 32), 256>>>(p_h1, ffn_w3, ffn_b3, p_y, out,
                                              NB, DD, HID);
}

// round 7
// speedup vs baseline: 1.2094x; 1.2094x over previous
#include <cuda_runtime.h>
#include <cuda_bf16.h>

// Shapes (compile-time constants)
#define NB   512           // sequence length
#define DD   256           // model dim
#define HH   8             // heads
#define HID  682           // swiglu hidden
#define QKVD 768

typedef unsigned long long u64;

// ---------------- device scratch ----------------
__device__ float g_xn[NB * DD];
__device__ float g_qkv[NB * QKVD];
__device__ float2 g_PKT[DD * NB];    // (.x = K^T[k][j], .y = Pb^T[k][j])
__device__ float g_Pb[NB * DD];
__device__ float g_Pv[NB * DD];
__device__ float g_rv2T[DD * DD];    // rv2 transposed [k][d]
__device__ float g_w[NB * NB * HH];  // softmax weights [i][j*HH+h]  (8MB)
__device__ float g_y[NB * DD];
__device__ float g_xn2[NB * DD];
__device__ float g_h1[NB * HID];

// ---- packed f32x2 helpers (sm_100+) ----
__device__ __forceinline__ u64 pk2(float lo, float hi) {
    u64 r;
    asm("mov.b64 %0, {%1, %2};" : "=l"(r) : "f"(lo), "f"(hi));
    return r;
}
__device__ __forceinline__ float2 up2(u64 v) {
    float2 f;
    asm("mov.b64 {%0, %1}, %2;" : "=f"(f.x), "=f"(f.y) : "l"(v));
    return f;
}
__device__ __forceinline__ u64 fma2(u64 a, u64 b, u64 c) {
    u64 d;
    asm("fma.rn.f32x2 %0, %1, %2, %3;" : "=l"(d) : "l"(a), "l"(b), "l"(c));
    return d;
}
__device__ __forceinline__ u64 add2(u64 a, u64 b) {
    u64 d;
    asm("add.rn.f32x2 %0, %1, %2;" : "=l"(d) : "l"(a), "l"(b));
    return d;
}

// fast silu via MUFU.TANH: v * (0.5*tanh(v/2) + 0.5)  -- 1 MUFU
__device__ __forceinline__ float silu_f(float v) {
    float t;
    asm("tanh.approx.f32 %0, %1;" : "=f"(t) : "f"(v * 0.5f));
    return v * fmaf(t, 0.5f, 0.5f);
}
// accurate silu for the (cold) FFN epilogue
__device__ __forceinline__ float silu_acc(float v) {
    return v / (1.0f + __expf(-v));
}

// ---------------- LayerNorm: one block per row, 256 threads ----------------
__global__ __launch_bounds__(256) void ln_kernel(const float* __restrict__ x,
                                                 const float* __restrict__ w,
                                                 const float* __restrict__ b,
                                                 float* __restrict__ out) {
    int row = blockIdx.x, t = threadIdx.x;
    float v = x[row * DD + t];
    float s = v, q = v * v;
#pragma unroll
    for (int o = 16; o; o >>= 1) {
        s += __shfl_xor_sync(0xffffffff, s, o);
        q += __shfl_xor_sync(0xffffffff, q, o);
    }
    __shared__ float ss[8], sq[8];
    int warp = t >> 5, lane = t & 31;
    if (lane == 0) { ss[warp] = s; sq[warp] = q; }
    __syncthreads();
    s = 0.f; q = 0.f;
#pragma unroll
    for (int k = 0; k < 8; k++) { s += ss[k]; q += sq[k]; }
    float mean = s * (1.0f / DD);
    float var = q * (1.0f / DD) - mean * mean;
    out[row * DD + t] = (v - mean) * rsqrtf(var + 1e-5f) * w[t] + b[t];
}

// ---------------- coords projection ----------------
__global__ __launch_bounds__(256) void proj3_kernel(const float* __restrict__ coords,
                                                    const float* __restrict__ rb1,
                                                    const float* __restrict__ rv1,
                                                    float* __restrict__ Pb,
                                                    float2* __restrict__ PKT,
                                                    float* __restrict__ Pv) {
    int i = blockIdx.x, k = threadIdx.x;
    float c0 = coords[i * 3 + 0], c1 = coords[i * 3 + 1], c2 = coords[i * 3 + 2];
    float pb = rb1[k * 3 + 0] * c0 + rb1[k * 3 + 1] * c1 + rb1[k * 3 + 2] * c2;
    float pv = rv1[k * 3 + 0] * c0 + rv1[k * 3 + 1] * c1 + rv1[k * 3 + 2] * c2;
    Pb[i * DD + k] = pb;
    PKT[k * NB + i].y = pb;
    Pv[i * DD + k] = pv;
}

// ---------------- K^T pack: PKT[k][j].x = qkv[j][DD + k] ----------------
__global__ __launch_bounds__(256) void kt_pack_kernel(const float* __restrict__ qkv,
                                                      float2* __restrict__ PKT) {
    __shared__ float tile[32][33];
    int c0 = blockIdx.x * 32, r0 = blockIdx.y * 32;   // c = k dim, r = j dim
    int tx = threadIdx.x, ty = threadIdx.y;  // 32 x 8
#pragma unroll
    for (int s = 0; s < 32; s += 8)
        tile[ty + s][tx] = qkv[(r0 + ty + s) * QKVD + DD + c0 + tx];
    __syncthreads();
#pragma unroll
    for (int s = 0; s < 32; s += 8)
        PKT[(c0 + ty + s) * NB + r0 + tx].x = tile[tx][ty + s];
}

// ---------------- generic 32x32-tiled transpose ----------------
__global__ __launch_bounds__(256) void transpose_kernel(const float* __restrict__ in,
                                                        float* __restrict__ out,
                                                        int R, int C, int ldin, int off) {
    __shared__ float tile[32][33];
    int c0 = blockIdx.x * 32, r0 = blockIdx.y * 32;
    int tx = threadIdx.x, ty = threadIdx.y;  // 32 x 8
#pragma unroll
    for (int s = 0; s < 32; s += 8)
        tile[ty + s][tx] = in[(r0 + ty + s) * ldin + off + c0 + tx];
    __syncthreads();
#pragma unroll
    for (int s = 0; s < 32; s += 8)
        out[(c0 + ty + s) * R + r0 + tx] = tile[tx][ty + s];
}

// ---------------- GEMM: C = A @ W^T (+bias)(+residual), 32x64 tile ----------------
__global__ __launch_bounds__(256, 2) void gemm_t(const float* __restrict__ A,
                                                 const float* __restrict__ W,
                                                 const float* __restrict__ bias,
                                                 const float* __restrict__ residual,
                                                 float* __restrict__ C,
                                                 int M, int N, int K) {
    __shared__ __align__(16) u64 As[32][34];     // [k][m] duplicated
    __shared__ __align__(16) float Ws[32][68];   // [k][n]
    int tid = threadIdx.x;
    int tx = tid & 15, ty = tid >> 4;            // tx -> n (4 cols), ty -> m (2 rows)
    int row0 = blockIdx.y * 32, col0 = blockIdx.x * 64;
    u64 acc[2][2] = {};
    for (int k0 = 0; k0 < K; k0 += 32) {
#pragma unroll
        for (int l = 0; l < 4; l++) {            // A: 32x32
            int idx = l * 256 + tid;
            int m = idx >> 5, k = idx & 31;
            int gk = k0 + k, ar = row0 + m;
            float v = (ar < M && gk < K) ? A[ar * K + gk] : 0.f;
            As[k][m] = pk2(v, v);
        }
#pragma unroll
        for (int l = 0; l < 8; l++) {            // W: 64x32
            int idx = l * 256 + tid;
            int m = idx >> 5, k = idx & 31;
            int gk = k0 + k, wr = col0 + m;
            Ws[k][m] = (wr < N && gk < K) ? W[wr * K + gk] : 0.f;
        }
        __syncthreads();
#pragma unroll
        for (int kk = 0; kk < 32; kk++) {
            ulonglong2 Av = *(const ulonglong2*)&As[kk][ty * 2];
            ulonglong2 Bv = *(const ulonglong2*)&Ws[kk][tx * 4];
            acc[0][0] = fma2(Av.x, Bv.x, acc[0][0]);
            acc[0][1] = fma2(Av.x, Bv.y, acc[0][1]);
            acc[1][0] = fma2(Av.y, Bv.x, acc[1][0]);
            acc[1][1] = fma2(Av.y, Bv.y, acc[1][1]);
        }
        __syncthreads();
    }
#pragma unroll
    for (int r = 0; r < 2; r++) {
        int m = row0 + ty * 2 + r;
        if (m >= M) continue;
#pragma unroll
        for (int c2 = 0; c2 < 2; c2++) {
            float2 v = up2(acc[r][c2]);
            int n0 = col0 + tx * 4 + c2 * 2;
            if (n0 < N) {
                float o = v.x;
                if (bias) o += bias[n0];
                if (residual) o += residual[m * N + n0];
                C[m * N + n0] = o;
            }
            if (n0 + 1 < N) {
                float o = v.y;
                if (bias) o += bias[n0 + 1];
                if (residual) o += residual[m * N + n0 + 1];
                C[m * N + n0 + 1] = o;
            }
        }
    }
}

// ---------------- GEMM 32x32 tile (better grid fill for small N) ----------------
__global__ __launch_bounds__(256, 3) void gemm_t32(const float* __restrict__ A,
                                                   const float* __restrict__ W,
                                                   const float* __restrict__ bias,
                                                   const float* __restrict__ residual,
                                                   float* __restrict__ C,
                                                   int M, int N, int K) {
    __shared__ __align__(16) u64 As[32][34];     // [k][m] duplicated
    __shared__ __align__(16) float Ws[32][36];   // [k][n]
    int tid = threadIdx.x;
    int tx = tid & 7, ty = tid >> 3;             // tx -> n (4 cols), ty -> m (1 row)
    int row0 = blockIdx.y * 32, col0 = blockIdx.x * 32;
    u64 acc[2] = {};
    for (int k0 = 0; k0 < K; k0 += 32) {
#pragma unroll
        for (int l = 0; l < 4; l++) {
            int idx = l * 256 + tid;
            int m = idx >> 5, k = idx & 31;
            int gk = k0 + k;
            int ar = row0 + m, wr = col0 + m;
            float va = (ar < M && gk < K) ? A[ar * K + gk] : 0.f;
            As[k][m] = pk2(va, va);
            Ws[k][m] = (wr < N && gk < K) ? W[wr * K + gk] : 0.f;
        }
        __syncthreads();
#pragma unroll
        for (int kk = 0; kk < 32; kk++) {
            u64 Av = As[kk][ty];
            ulonglong2 Bv = *(const ulonglong2*)&Ws[kk][tx * 4];
            acc[0] = fma2(Av, Bv.x, acc[0]);
            acc[1] = fma2(Av, Bv.y, acc[1]);
        }
        __syncthreads();
    }
    int m = row0 + ty;
    if (m < M) {
#pragma unroll
        for (int c2 = 0; c2 < 2; c2++) {
            float2 v = up2(acc[c2]);
            int n0 = col0 + tx * 4 + c2 * 2;
            if (n0 < N) {
                float o = v.x;
                if (bias) o += bias[n0];
                if (residual) o += residual[m * N + n0];
                C[m * N + n0] = o;
            }
            if (n0 + 1 < N) {
                float o = v.y;
                if (bias) o += bias[n0 + 1];
                if (residual) o += residual[m * N + n0 + 1];
                C[m * N + n0 + 1] = o;
            }
        }
    }
}

// ---------------- fused SwiGLU dual-GEMM, 32x64 tile ----------------
__global__ __launch_bounds__(256, 2) void gemm_swiglu(const float* __restrict__ A,
                                                      const float* __restrict__ W1,
                                                      const float* __restrict__ b1,
                                                      const float* __restrict__ W2,
                                                      const float* __restrict__ b2,
                                                      float* __restrict__ Hout,
                                                      int M, int N, int K) {
    __shared__ __align__(16) u64 As[32][34];
    __shared__ __align__(16) float W1s[32][68];
    __shared__ __align__(16) float W2s[32][68];
    int tid = threadIdx.x;
    int tx = tid & 15, ty = tid >> 4;
    int row0 = blockIdx.y * 32, col0 = blockIdx.x * 64;
    u64 acc1[2][2] = {};
    u64 acc2[2][2] = {};
    for (int k0 = 0; k0 < K; k0 += 32) {
#pragma unroll
        for (int l = 0; l < 4; l++) {
            int idx = l * 256 + tid;
            int m = idx >> 5, k = idx & 31;
            int gk = k0 + k, ar = row0 + m;
            float v = (ar < M && gk < K) ? A[ar * K + gk] : 0.f;
            As[k][m] = pk2(v, v);
        }
#pragma unroll
        for (int l = 0; l < 8; l++) {
            int idx = l * 256 + tid;
            int m = idx >> 5, k = idx & 31;
            int gk = k0 + k, wr = col0 + m;
            W1s[k][m] = (wr < N && gk < K) ? W1[wr * K + gk] : 0.f;
            W2s[k][m] = (wr < N && gk < K) ? W2[wr * K + gk] : 0.f;
        }
        __syncthreads();
#pragma unroll
        for (int kk = 0; kk < 32; kk++) {
            ulonglong2 Av = *(const ulonglong2*)&As[kk][ty * 2];
            ulonglong2 Bv = *(const ulonglong2*)&W1s[kk][tx * 4];
            ulonglong2 Cv = *(const ulonglong2*)&W2s[kk][tx * 4];
            acc1[0][0] = fma2(Av.x, Bv.x, acc1[0][0]);
            acc1[0][1] = fma2(Av.x, Bv.y, acc1[0][1]);
            acc1[1][0] = fma2(Av.y, Bv.x, acc1[1][0]);
            acc1[1][1] = fma2(Av.y, Bv.y, acc1[1][1]);
            acc2[0][0] = fma2(Av.x, Cv.x, acc2[0][0]);
            acc2[0][1] = fma2(Av.x, Cv.y, acc2[0][1]);
            acc2[1][0] = fma2(Av.y, Cv.x, acc2[1][0]);
            acc2[1][1] = fma2(Av.y, Cv.y, acc2[1][1]);
        }
        __syncthreads();
    }
#pragma unroll
    for (int r = 0; r < 2; r++) {
        int m = row0 + ty * 2 + r;
        if (m >= M) continue;
#pragma unroll
        for (int c2 = 0; c2 < 2; c2++) {
            float2 v1 = up2(acc1[r][c2]);
            float2 v2 = up2(acc2[r][c2]);
            int n0 = col0 + tx * 4 + c2 * 2;
            if (n0 < N)
                Hout[m * N + n0] = silu_acc(v1.x + b1[n0]) * (v2.x + b2[n0]);
            if (n0 + 1 < N)
                Hout[m * N + n0 + 1] = silu_acc(v1.y + b1[n0 + 1]) * (v2.y + b2[n0 + 1]);
        }
    }
}

// ---------------- attention part 1: logits + softmax -> g_w ----------------
__global__ __launch_bounds__(256, 3) void attn_logits(
    const float* __restrict__ qkv, const float2* __restrict__ PKT,
    const float* __restrict__ Pb, const float* __restrict__ rb1_b,
    const float* __restrict__ rb2_w, const float* __restrict__ rb2_b,
    float* __restrict__ gw_all) {
    const int i0 = blockIdx.x * 2;
    const int t = threadIdx.x;

    __shared__ __align__(16) float2 sm_qpq[2][DD];     // (q[k], Pbq[k]) per query
    __shared__ __align__(16) float sm_rb2[DD * HH];    // rb2 transposed [k][h]
    __shared__ __align__(16) float sm_w[2][NB * HH];   // logits -> weights [q][j][h]

#pragma unroll
    for (int q = 0; q < 2; q++) {
        int iq = i0 + q;
        sm_qpq[q][t] = make_float2(qkv[iq * QKVD + t], Pb[iq * DD + t] + rb1_b[t]);
    }
#pragma unroll
    for (int h = 0; h < HH; h++) sm_rb2[t * HH + h] = rb2_w[h * DD + t];
    __syncthreads();

    // ---- Phase A: logits for (q in {0,1}) x (j0 = t, j1 = t+256) ----
    {
        const int j0 = t, j1 = t + 256;
        u64 bias[2][2][4] = {};   // [q][jslot][head pair]
        const float sc = 0.17677669529663687f;
#pragma unroll
        for (int h = 0; h < HH; h++) {
            u64 qk[2] = {0ull, 0ull};   // packed over (j0, j1)
#pragma unroll 4
            for (int kk = 0; kk < 32; kk++) {
                int k = h * 32 + kk;
                float2 pk0 = PKT[k * NB + j0];
                float2 pk1 = PKT[k * NB + j1];
                u64 kvp = pk2(pk0.x, pk1.x);
                ulonglong2 rA = *(const ulonglong2*)(sm_rb2 + k * HH);
                ulonglong2 rB = *(const ulonglong2*)(sm_rb2 + k * HH + 4);
#pragma unroll
                for (int q = 0; q < 2; q++) {
                    float2 qp = sm_qpq[q][k];
                    qk[q] = fma2(pk2(qp.x, qp.x), kvp, qk[q]);
                    float u0 = silu_f(qp.y - pk0.y);
                    float u1 = silu_f(qp.y - pk1.y);
                    u64 u0p = pk2(u0, u0);
                    u64 u1p = pk2(u1, u1);
                    bias[q][0][0] = fma2(u0p, rA.x, bias[q][0][0]);
                    bias[q][0][1] = fma2(u0p, rA.y, bias[q][0][1]);
                    bias[q][0][2] = fma2(u0p, rB.x, bias[q][0][2]);
                    bias[q][0][3] = fma2(u0p, rB.y, bias[q][0][3]);
                    bias[q][1][0] = fma2(u1p, rA.x, bias[q][1][0]);
                    bias[q][1][1] = fma2(u1p, rA.y, bias[q][1][1]);
                    bias[q][1][2] = fma2(u1p, rB.x, bias[q][1][2]);
                    bias[q][1][3] = fma2(u1p, rB.y, bias[q][1][3]);
                }
            }
            // fold qk*sc into bias pair c = h>>1, slot h&1
            int c = h >> 1;
#pragma unroll
            for (int q = 0; q < 2; q++) {
                float2 qv = up2(qk[q]);
                float s0 = qv.x * sc, s1 = qv.y * sc;
                u64 p0 = (h & 1) ? pk2(0.f, s0) : pk2(s0, 0.f);
                u64 p1 = (h & 1) ? pk2(0.f, s1) : pk2(s1, 0.f);
                bias[q][0][c] = add2(bias[q][0][c], p0);
                bias[q][1][c] = add2(bias[q][1][c], p1);
            }
        }
#pragma unroll
        for (int c = 0; c < 4; c++) {
            u64 bb = pk2(rb2_b[2 * c], rb2_b[2 * c + 1]);
            *(u64*)(&sm_w[0][j0 * HH + 2 * c]) = add2(bias[0][0][c], bb);
            *(u64*)(&sm_w[0][j1 * HH + 2 * c]) = add2(bias[0][1][c], bb);
            *(u64*)(&sm_w[1][j0 * HH + 2 * c]) = add2(bias[1][0][c], bb);
            *(u64*)(&sm_w[1][j1 * HH + 2 * c]) = add2(bias[1][1][c], bb);
        }
    }
    __syncthreads();

    // ---- softmax: warp h handles head h, loop over both queries ----
    {
        int h = t >> 5, lane = t & 31;
#pragma unroll
        for (int q = 0; q < 2; q++) {
            float* wq = sm_w[q];
            float m = -1e30f;
            for (int j = lane; j < NB; j += 32) m = fmaxf(m, wq[j * HH + h]);
#pragma unroll
            for (int o = 16; o; o >>= 1) m = fmaxf(m, __shfl_xor_sync(0xffffffff, m, o));
            float s = 0.f;
            for (int j = lane; j < NB; j += 32) {
                float e = __expf(wq[j * HH + h] - m);
                wq[j * HH + h] = e;
                s += e;
            }
#pragma unroll
            for (int o = 16; o; o >>= 1) s += __shfl_xor_sync(0xffffffff, s, o);
            float inv = 1.0f / s;
            for (int j = lane; j < NB; j += 32) wq[j * HH + h] *= inv;
        }
    }
    __syncthreads();

    // ---- bulk copy weights to gmem ----
    {
        float4* dst = (float4*)(gw_all + i0 * NB * HH);
        const float4* src = (const float4*)sm_w;
#pragma unroll
        for (int idx = t; idx < 2 * NB * HH / 4; idx += 256) dst[idx] = src[idx];
    }
}

// ---------------- attention part 2: T accumulation + context + output ---------------
// 2 queries per block (proven occ-3, no-spill shape)
__global__ __launch_bounds__(256, 3) void attn_out(
    const float* __restrict__ x, const float* __restrict__ qkv,
    const float* __restrict__ Pv, const float* __restrict__ rv1_b,
    const float* __restrict__ rv2T, const float* __restrict__ rv2_b,
    const float* __restrict__ gw_all, float* __restrict__ y) {
    const int i0 = blockIdx.x * 2;
    const int t = threadIdx.x;

    __shared__ __align__(16) float sm_T[2][HH * DD];   // [q][h][k], 16KB

    const float* gw0 = gw_all + i0 * NB * HH;
    const float* gw1 = gw0 + NB * HH;

    // ---- Phase B: T[q][h,k], thread t owns k = t ----
    {
        float pvb = rv1_b[t];
        float pvq0 = Pv[i0 * DD + t] + pvb;
        float pvq1 = Pv[(i0 + 1) * DD + t] + pvb;
        u64 T0[4] = {}, T1[4] = {};
#pragma unroll 2
        for (int j = 0; j < NB; j++) {
            float pv = Pv[j * DD + t];
            float s0 = silu_f(pvq0 - pv);
            float s1 = silu_f(pvq1 - pv);
            u64 s0p = pk2(s0, s0), s1p = pk2(s1, s1);
            ulonglong2 wA0 = *(const ulonglong2*)(gw0 + j * HH);
            ulonglong2 wA1 = *(const ulonglong2*)(gw0 + j * HH + 4);
            ulonglong2 wB0 = *(const ulonglong2*)(gw1 + j * HH);
            ulonglong2 wB1 = *(const ulonglong2*)(gw1 + j * HH + 4);
            T0[0] = fma2(s0p, wA0.x, T0[0]); T0[1] = fma2(s0p, wA0.y, T0[1]);
            T0[2] = fma2(s0p, wA1.x, T0[2]); T0[3] = fma2(s0p, wA1.y, T0[3]);
            T1[0] = fma2(s1p, wB0.x, T1[0]); T1[1] = fma2(s1p, wB0.y, T1[1]);
            T1[2] = fma2(s1p, wB1.x, T1[2]); T1[3] = fma2(s1p, wB1.y, T1[3]);
        }
#pragma unroll
        for (int c = 0; c < 4; c++) {
            float2 a = up2(T0[c]);
            sm_T[0][(2 * c) * DD + t] = a.x;
            sm_T[0][(2 * c + 1) * DD + t] = a.y;
            float2 b = up2(T1[c]);
            sm_T[1][(2 * c) * DD + t] = b.x;
            sm_T[1][(2 * c + 1) * DD + t] = b.y;
        }
    }
    __syncthreads();

    // ---- output: context1 + context2 + residual, for both queries ----
    {
        const int d = t;
        const int h = d >> 5;
        float c1a = 0.f, c1b = 0.f;
        const float* V = qkv + 2 * DD;
#pragma unroll 8
        for (int j = 0; j < NB; j++) {
            float v = V[j * QKVD + d];
            c1a += gw0[j * HH + h] * v;
            c1b += gw1[j * HH + h] * v;
        }
        float bv = rv2_b[d];
        float c2a = bv, c2b = bv;
        const float* T0s = sm_T[0] + h * DD;
        const float* T1s = sm_T[1] + h * DD;
#pragma unroll 8
        for (int k = 0; k < DD; k++) {
            float rv = rv2T[k * DD + d];
            c2a += rv * T0s[k];
            c2b += rv * T1s[k];
        }
        y[i0 * DD + d] = x[i0 * DD + d] + c1a + c2a;
        y[(i0 + 1) * DD + d] = x[(i0 + 1) * DD + d] + c1b + c2b;
    }
}

// ---------------- host launcher ----------------
extern "C" void kernel_launch(void* const* d_in, const int* in_sizes, int n_in,
                              void* d_out, int out_size) {
    const float* x      = (const float*)d_in[0];
    const float* coords = (const float*)d_in[1];
    const float* ln1_w  = (const float*)d_in[2];
    const float* ln1_b  = (const float*)d_in[3];
    const float* ln2_w  = (const float*)d_in[4];
    const float* ln2_b  = (const float*)d_in[5];
    const float* qkv_w  = (const float*)d_in[6];
    const float* qkv_b  = (const float*)d_in[7];
    const float* rb1_w  = (const float*)d_in[8];
    const float* rb1_b  = (const float*)d_in[9];
    const float* rb2_w  = (const float*)d_in[10];
    const float* rb2_b  = (const float*)d_in[11];
    const float* rv1_w  = (const float*)d_in[12];
    const float* rv1_b  = (const float*)d_in[13];
    const float* rv2_w  = (const float*)d_in[14];
    const float* rv2_b  = (const float*)d_in[15];
    const float* ffn_w1 = (const float*)d_in[16];
    const float* ffn_b1 = (const float*)d_in[17];
    const float* ffn_w2 = (const float*)d_in[18];
    const float* ffn_b2 = (const float*)d_in[19];
    const float* ffn_w3 = (const float*)d_in[20];
    const float* ffn_b3 = (const float*)d_in[21];
    float* out = (float*)d_out;

    float *p_xn, *p_qkv, *p_Pb, *p_Pv, *p_rv2T, *p_w, *p_y, *p_xn2, *p_h1;
    float2* p_PKT;
    cudaGetSymbolAddress((void**)&p_xn, g_xn);
    cudaGetSymbolAddress((void**)&p_qkv, g_qkv);
    cudaGetSymbolAddress((void**)&p_PKT, g_PKT);
    cudaGetSymbolAddress((void**)&p_Pb, g_Pb);
    cudaGetSymbolAddress((void**)&p_Pv, g_Pv);
    cudaGetSymbolAddress((void**)&p_rv2T, g_rv2T);
    cudaGetSymbolAddress((void**)&p_w, g_w);
    cudaGetSymbolAddress((void**)&p_y, g_y);
    cudaGetSymbolAddress((void**)&p_xn2, g_xn2);
    cudaGetSymbolAddress((void**)&p_h1, g_h1);

    dim3 tthr(32, 8);

    // 1. LN1
    ln_kernel<<<NB, 256>>>(x, ln1_w, ln1_b, p_xn);
    // 2. QKV = xn @ qkv_w^T + qkv_b    [512,768]
    gemm_t<<<dim3(QKVD / 64, NB / 32), 256>>>(p_xn, qkv_w, qkv_b, nullptr, p_qkv,
                                              NB, QKVD, DD);
    // 3. coords projections (Pb, PKT.y, Pv)
    proj3_kernel<<<NB, 256>>>(coords, rb1_w, rv1_w, p_Pb, p_PKT, p_Pv);
    // 4. K^T pack into PKT.x, rv2^T
    kt_pack_kernel<<<dim3(DD / 32, NB / 32), tthr>>>(p_qkv, p_PKT);
    transpose_kernel<<<dim3(DD / 32, DD / 32), tthr>>>(rv2_w, p_rv2T, DD, DD, DD, 0);
    // 5. attention part 1: logits + softmax
    attn_logits<<<NB / 2, 256>>>(p_qkv, p_PKT, p_Pb, rb1_b, rb2_w, rb2_b, p_w);
    // 6. attention part 2: T + context + output (y = x + attn_out)
    attn_out<<<NB / 2, 256>>>(x, p_qkv, p_Pv, rv1_b, p_rv2T, rv2_b, p_w, p_y);
    // 7. LN2
    ln_kernel<<<NB, 256>>>(p_y, ln2_w, ln2_b, p_xn2);
    // 8. fused SwiGLU dual-GEMM
    gemm_swiglu<<<dim3((HID + 63) / 64, NB / 32), 256>>>(p_xn2, ffn_w1, ffn_b1,
                                                         ffn_w2, ffn_b2, p_h1,
                                                         NB, HID, DD);
    // 9. out = h1 @ ffn_w3^T + ffn_b3 + y   (32x32 tiles -> 128 blocks)
    gemm_t32<<<dim3(DD / 32, NB / 32), 256>>>(p_h1, ffn_w3, ffn_b3, p_y, out,
                                              NB, DD, HID);
}

// round 8
// speedup vs baseline: 1.2710x; 1.0509x over previous
#include <cuda_runtime.h>
#include <cuda_bf16.h>

// Shapes (compile-time constants)
#define NB   512           // sequence length
#define DD   256           // model dim
#define HH   8             // heads
#define HID  682           // swiglu hidden
#define QKVD 768

typedef unsigned long long u64;

// ---------------- device scratch ----------------
__device__ float g_xn[NB * DD];
__device__ float g_qkv[NB * QKVD];
__device__ float2 g_PKT[DD * NB];    // (.x = K^T[k][j], .y = 0.5*Pb^T[k][j])
__device__ float g_Pb[NB * DD];      // 0.5 * Pb
__device__ float g_Pv[NB * DD];      // 0.5 * Pv
__device__ float g_rv2T[DD * DD];    // rv2 transposed [k][d]
__device__ float g_w[NB * NB * HH];  // softmax weights [i][j*HH+h]  (8MB)
__device__ float g_y[NB * DD];
__device__ float g_xn2[NB * DD];
__device__ float g_h1[NB * HID];

// ---- packed f32x2 helpers (sm_100+) ----
__device__ __forceinline__ u64 pk2(float lo, float hi) {
    u64 r;
    asm("mov.b64 %0, {%1, %2};" : "=l"(r) : "f"(lo), "f"(hi));
    return r;
}
__device__ __forceinline__ float2 up2(u64 v) {
    float2 f;
    asm("mov.b64 {%0, %1}, %2;" : "=f"(f.x), "=f"(f.y) : "l"(v));
    return f;
}
__device__ __forceinline__ u64 fma2(u64 a, u64 b, u64 c) {
    u64 d;
    asm("fma.rn.f32x2 %0, %1, %2, %3;" : "=l"(d) : "l"(a), "l"(b), "l"(c));
    return d;
}
__device__ __forceinline__ u64 add2(u64 a, u64 b) {
    u64 d;
    asm("add.rn.f32x2 %0, %1, %2;" : "=l"(d) : "l"(a), "l"(b));
    return d;
}

// silu from the HALF-difference s = 0.5*(a-b):
// silu(a-b) = (a-b)*sigmoid(a-b) = 2s*0.5*(tanh(s)+1) = s*tanh(s)+s
__device__ __forceinline__ float silu_h(float s) {
    float t;
    asm("tanh.approx.f32 %0, %1;" : "=f"(t) : "f"(s));
    return fmaf(s, t, s);
}
// accurate silu for the (cold) FFN epilogue
__device__ __forceinline__ float silu_acc(float v) {
    return v / (1.0f + __expf(-v));
}

// ---------------- LayerNorm: one block per row, 256 threads ----------------
__global__ __launch_bounds__(256) void ln_kernel(const float* __restrict__ x,
                                                 const float* __restrict__ w,
                                                 const float* __restrict__ b,
                                                 float* __restrict__ out) {
    int row = blockIdx.x, t = threadIdx.x;
    float v = x[row * DD + t];
    float s = v, q = v * v;
#pragma unroll
    for (int o = 16; o; o >>= 1) {
        s += __shfl_xor_sync(0xffffffff, s, o);
        q += __shfl_xor_sync(0xffffffff, q, o);
    }
    __shared__ float ss[8], sq[8];
    int warp = t >> 5, lane = t & 31;
    if (lane == 0) { ss[warp] = s; sq[warp] = q; }
    __syncthreads();
    s = 0.f; q = 0.f;
#pragma unroll
    for (int k = 0; k < 8; k++) { s += ss[k]; q += sq[k]; }
    float mean = s * (1.0f / DD);
    float var = q * (1.0f / DD) - mean * mean;
    out[row * DD + t] = (v - mean) * rsqrtf(var + 1e-5f) * w[t] + b[t];
}

// ---------------- coords projection (all outputs HALF-scaled) ----------------
__global__ __launch_bounds__(256) void proj3_kernel(const float* __restrict__ coords,
                                                    const float* __restrict__ rb1,
                                                    const float* __restrict__ rv1,
                                                    float* __restrict__ Pb,
                                                    float2* __restrict__ PKT,
                                                    float* __restrict__ Pv) {
    int i = blockIdx.x, k = threadIdx.x;
    float c0 = coords[i * 3 + 0], c1 = coords[i * 3 + 1], c2 = coords[i * 3 + 2];
    float pb = rb1[k * 3 + 0] * c0 + rb1[k * 3 + 1] * c1 + rb1[k * 3 + 2] * c2;
    float pv = rv1[k * 3 + 0] * c0 + rv1[k * 3 + 1] * c1 + rv1[k * 3 + 2] * c2;
    Pb[i * DD + k] = 0.5f * pb;
    PKT[k * NB + i].y = 0.5f * pb;
    Pv[i * DD + k] = 0.5f * pv;
}

// ---------------- generic 32x32-tiled transpose ----------------
__global__ __launch_bounds__(256) void transpose_kernel(const float* __restrict__ in,
                                                        float* __restrict__ out,
                                                        int R, int C, int ldin, int off) {
    __shared__ float tile[32][33];
    int c0 = blockIdx.x * 32, r0 = blockIdx.y * 32;
    int tx = threadIdx.x, ty = threadIdx.y;  // 32 x 8
#pragma unroll
    for (int s = 0; s < 32; s += 8)
        tile[ty + s][tx] = in[(r0 + ty + s) * ldin + off + c0 + tx];
    __syncthreads();
#pragma unroll
    for (int s = 0; s < 32; s += 8)
        out[(c0 + ty + s) * R + r0 + tx] = tile[tx][ty + s];
}

// ---------------- GEMM: C = A @ W^T (+bias), 32x64 tile; optional K^T side-write ----
__global__ __launch_bounds__(256, 2) void gemm_t(const float* __restrict__ A,
                                                 const float* __restrict__ W,
                                                 const float* __restrict__ bias,
                                                 float2* __restrict__ PKT,  // nullable
                                                 float* __restrict__ C,
                                                 int M, int N, int K) {
    __shared__ __align__(16) u64 As[32][34];     // [k][m] duplicated
    __shared__ __align__(16) float Ws[32][68];   // [k][n]
    int tid = threadIdx.x;
    int tx = tid & 15, ty = tid >> 4;            // tx -> n (4 cols), ty -> m (2 rows)
    int row0 = blockIdx.y * 32, col0 = blockIdx.x * 64;
    u64 acc[2][2] = {};
    for (int k0 = 0; k0 < K; k0 += 32) {
#pragma unroll
        for (int l = 0; l < 4; l++) {            // A: 32x32
            int idx = l * 256 + tid;
            int m = idx >> 5, k = idx & 31;
            int gk = k0 + k, ar = row0 + m;
            float v = (ar < M && gk < K) ? A[ar * K + gk] : 0.f;
            As[k][m] = pk2(v, v);
        }
#pragma unroll
        for (int l = 0; l < 8; l++) {            // W: 64x32
            int idx = l * 256 + tid;
            int m = idx >> 5, k = idx & 31;
            int gk = k0 + k, wr = col0 + m;
            Ws[k][m] = (wr < N && gk < K) ? W[wr * K + gk] : 0.f;
        }
        __syncthreads();
#pragma unroll
        for (int kk = 0; kk < 32; kk++) {
            ulonglong2 Av = *(const ulonglong2*)&As[kk][ty * 2];
            ulonglong2 Bv = *(const ulonglong2*)&Ws[kk][tx * 4];
            acc[0][0] = fma2(Av.x, Bv.x, acc[0][0]);
            acc[0][1] = fma2(Av.x, Bv.y, acc[0][1]);
            acc[1][0] = fma2(Av.y, Bv.x, acc[1][0]);
            acc[1][1] = fma2(Av.y, Bv.y, acc[1][1]);
        }
        __syncthreads();
    }
#pragma unroll
    for (int r = 0; r < 2; r++) {
        int m = row0 + ty * 2 + r;
        if (m >= M) continue;
#pragma unroll
        for (int c2 = 0; c2 < 2; c2++) {
            float2 v = up2(acc[r][c2]);
            int n0 = col0 + tx * 4 + c2 * 2;
            if (n0 < N) {
                float o = v.x + (bias ? bias[n0] : 0.f);
                C[m * N + n0] = o;
                if (PKT && n0 >= DD && n0 < 2 * DD) PKT[(n0 - DD) * NB + m].x = o;
            }
            if (n0 + 1 < N) {
                float o = v.y + (bias ? bias[n0 + 1] : 0.f);
                C[m * N + n0 + 1] = o;
                if (PKT && n0 + 1 >= DD && n0 + 1 < 2 * DD) PKT[(n0 + 1 - DD) * NB + m].x = o;
            }
        }
    }
}

// ---------------- GEMM 32x32 tile (better grid fill for small N) ----------------
__global__ __launch_bounds__(256, 3) void gemm_t32(const float* __restrict__ A,
                                                   const float* __restrict__ W,
                                                   const float* __restrict__ bias,
                                                   const float* __restrict__ residual,
                                                   float* __restrict__ C,
                                                   int M, int N, int K) {
    __shared__ __align__(16) u64 As[32][34];     // [k][m] duplicated
    __shared__ __align__(16) float Ws[32][36];   // [k][n]
    int tid = threadIdx.x;
    int tx = tid & 7, ty = tid >> 3;             // tx -> n (4 cols), ty -> m (1 row)
    int row0 = blockIdx.y * 32, col0 = blockIdx.x * 32;
    u64 acc[2] = {};
    for (int k0 = 0; k0 < K; k0 += 32) {
#pragma unroll
        for (int l = 0; l < 4; l++) {
            int idx = l * 256 + tid;
            int m = idx >> 5, k = idx & 31;
            int gk = k0 + k;
            int ar = row0 + m, wr = col0 + m;
            float va = (ar < M && gk < K) ? A[ar * K + gk] : 0.f;
            As[k][m] = pk2(va, va);
            Ws[k][m] = (wr < N && gk < K) ? W[wr * K + gk] : 0.f;
        }
        __syncthreads();
#pragma unroll
        for (int kk = 0; kk < 32; kk++) {
            u64 Av = As[kk][ty];
            ulonglong2 Bv = *(const ulonglong2*)&Ws[kk][tx * 4];
            acc[0] = fma2(Av, Bv.x, acc[0]);
            acc[1] = fma2(Av, Bv.y, acc[1]);
        }
        __syncthreads();
    }
    int m = row0 + ty;
    if (m < M) {
#pragma unroll
        for (int c2 = 0; c2 < 2; c2++) {
            float2 v = up2(acc[c2]);
            int n0 = col0 + tx * 4 + c2 * 2;
            if (n0 < N) {
                float o = v.x;
                if (bias) o += bias[n0];
                if (residual) o += residual[m * N + n0];
                C[m * N + n0] = o;
            }
            if (n0 + 1 < N) {
                float o = v.y;
                if (bias) o += bias[n0 + 1];
                if (residual) o += residual[m * N + n0 + 1];
                C[m * N + n0 + 1] = o;
            }
        }
    }
}

// ---------------- fused SwiGLU dual-GEMM, 32x64 tile ----------------
__global__ __launch_bounds__(256, 2) void gemm_swiglu(const float* __restrict__ A,
                                                      const float* __restrict__ W1,
                                                      const float* __restrict__ b1,
                                                      const float* __restrict__ W2,
                                                      const float* __restrict__ b2,
                                                      float* __restrict__ Hout,
                                                      int M, int N, int K) {
    __shared__ __align__(16) u64 As[32][34];
    __shared__ __align__(16) float W1s[32][68];
    __shared__ __align__(16) float W2s[32][68];
    int tid = threadIdx.x;
    int tx = tid & 15, ty = tid >> 4;
    int row0 = blockIdx.y * 32, col0 = blockIdx.x * 64;
    u64 acc1[2][2] = {};
    u64 acc2[2][2] = {};
    for (int k0 = 0; k0 < K; k0 += 32) {
#pragma unroll
        for (int l = 0; l < 4; l++) {
            int idx = l * 256 + tid;
            int m = idx >> 5, k = idx & 31;
            int gk = k0 + k, ar = row0 + m;
            float v = (ar < M && gk < K) ? A[ar * K + gk] : 0.f;
            As[k][m] = pk2(v, v);
        }
#pragma unroll
        for (int l = 0; l < 8; l++) {
            int idx = l * 256 + tid;
            int m = idx >> 5, k = idx & 31;
            int gk = k0 + k, wr = col0 + m;
            W1s[k][m] = (wr < N && gk < K) ? W1[wr * K + gk] : 0.f;
            W2s[k][m] = (wr < N && gk < K) ? W2[wr * K + gk] : 0.f;
        }
        __syncthreads();
#pragma unroll
        for (int kk = 0; kk < 32; kk++) {
            ulonglong2 Av = *(const ulonglong2*)&As[kk][ty * 2];
            ulonglong2 Bv = *(const ulonglong2*)&W1s[kk][tx * 4];
            ulonglong2 Cv = *(const ulonglong2*)&W2s[kk][tx * 4];
            acc1[0][0] = fma2(Av.x, Bv.x, acc1[0][0]);
            acc1[0][1] = fma2(Av.x, Bv.y, acc1[0][1]);
            acc1[1][0] = fma2(Av.y, Bv.x, acc1[1][0]);
            acc1[1][1] = fma2(Av.y, Bv.y, acc1[1][1]);
            acc2[0][0] = fma2(Av.x, Cv.x, acc2[0][0]);
            acc2[0][1] = fma2(Av.x, Cv.y, acc2[0][1]);
            acc2[1][0] = fma2(Av.y, Cv.x, acc2[1][0]);
            acc2[1][1] = fma2(Av.y, Cv.y, acc2[1][1]);
        }
        __syncthreads();
    }
#pragma unroll
    for (int r = 0; r < 2; r++) {
        int m = row0 + ty * 2 + r;
        if (m >= M) continue;
#pragma unroll
        for (int c2 = 0; c2 < 2; c2++) {
            float2 v1 = up2(acc1[r][c2]);
            float2 v2 = up2(acc2[r][c2]);
            int n0 = col0 + tx * 4 + c2 * 2;
            if (n0 < N)
                Hout[m * N + n0] = silu_acc(v1.x + b1[n0]) * (v2.x + b2[n0]);
            if (n0 + 1 < N)
                Hout[m * N + n0 + 1] = silu_acc(v1.y + b1[n0 + 1]) * (v2.y + b2[n0 + 1]);
        }
    }
}

// ---------------- attention part 1: logits + softmax -> g_w ----------------
__global__ __launch_bounds__(256, 3) void attn_logits(
    const float* __restrict__ qkv, const float2* __restrict__ PKT,
    const float* __restrict__ Pb, const float* __restrict__ rb1_b,
    const float* __restrict__ rb2_w, const float* __restrict__ rb2_b,
    float* __restrict__ gw_all) {
    const int i0 = blockIdx.x * 2;
    const int t = threadIdx.x;

    __shared__ __align__(16) float4 sm_qpq[DD];        // (q0, hpb0, q1, hpb1)
    __shared__ __align__(16) float sm_rb2[DD * HH];    // rb2 transposed [k][h]
    __shared__ __align__(16) float sm_w[2][NB * HH];   // logits -> weights [q][j][h]

    {
        float hb = 0.5f * rb1_b[t];
        sm_qpq[t] = make_float4(qkv[i0 * QKVD + t], Pb[i0 * DD + t] + hb,
                                qkv[(i0 + 1) * QKVD + t], Pb[(i0 + 1) * DD + t] + hb);
    }
#pragma unroll
    for (int h = 0; h < HH; h++) sm_rb2[t * HH + h] = rb2_w[h * DD + t];
    __syncthreads();

    // ---- Phase A: logits for (q in {0,1}) x (j0 = t, j1 = t+256) ----
    {
        const int j0 = t, j1 = t + 256;
        u64 bias[2][2][4] = {};   // [q][jslot][head pair]
        const float sc = 0.17677669529663687f;
#pragma unroll
        for (int h = 0; h < HH; h++) {
            u64 qk[2] = {0ull, 0ull};   // packed over (j0, j1)
#pragma unroll 4
            for (int kk = 0; kk < 32; kk++) {
                int k = h * 32 + kk;
                float2 pk0 = PKT[k * NB + j0];
                float2 pk1 = PKT[k * NB + j1];
                u64 kvp = pk2(pk0.x, pk1.x);
                ulonglong2 rA = *(const ulonglong2*)(sm_rb2 + k * HH);
                ulonglong2 rB = *(const ulonglong2*)(sm_rb2 + k * HH + 4);
                float4 qq = sm_qpq[k];
#pragma unroll
                for (int q = 0; q < 2; q++) {
                    float qv = q ? qq.z : qq.x;
                    float hy = q ? qq.w : qq.y;
                    qk[q] = fma2(pk2(qv, qv), kvp, qk[q]);
                    float u0 = silu_h(hy - pk0.y);
                    float u1 = silu_h(hy - pk1.y);
                    u64 u0p = pk2(u0, u0);
                    u64 u1p = pk2(u1, u1);
                    bias[q][0][0] = fma2(u0p, rA.x, bias[q][0][0]);
                    bias[q][0][1] = fma2(u0p, rA.y, bias[q][0][1]);
                    bias[q][0][2] = fma2(u0p, rB.x, bias[q][0][2]);
                    bias[q][0][3] = fma2(u0p, rB.y, bias[q][0][3]);
                    bias[q][1][0] = fma2(u1p, rA.x, bias[q][1][0]);
                    bias[q][1][1] = fma2(u1p, rA.y, bias[q][1][1]);
                    bias[q][1][2] = fma2(u1p, rB.x, bias[q][1][2]);
                    bias[q][1][3] = fma2(u1p, rB.y, bias[q][1][3]);
                }
            }
            // fold qk*sc into bias pair c = h>>1, slot h&1
            int c = h >> 1;
#pragma unroll
            for (int q = 0; q < 2; q++) {
                float2 qv = up2(qk[q]);
                float s0 = qv.x * sc, s1 = qv.y * sc;
                u64 p0 = (h & 1) ? pk2(0.f, s0) : pk2(s0, 0.f);
                u64 p1 = (h & 1) ? pk2(0.f, s1) : pk2(s1, 0.f);
                bias[q][0][c] = add2(bias[q][0][c], p0);
                bias[q][1][c] = add2(bias[q][1][c], p1);
            }
        }
#pragma unroll
        for (int c = 0; c < 4; c++) {
            u64 bb = pk2(rb2_b[2 * c], rb2_b[2 * c + 1]);
            *(u64*)(&sm_w[0][j0 * HH + 2 * c]) = add2(bias[0][0][c], bb);
            *(u64*)(&sm_w[0][j1 * HH + 2 * c]) = add2(bias[0][1][c], bb);
            *(u64*)(&sm_w[1][j0 * HH + 2 * c]) = add2(bias[1][0][c], bb);
            *(u64*)(&sm_w[1][j1 * HH + 2 * c]) = add2(bias[1][1][c], bb);
        }
    }
    __syncthreads();

    // ---- softmax: warp h handles head h, loop over both queries ----
    {
        int h = t >> 5, lane = t & 31;
#pragma unroll
        for (int q = 0; q < 2; q++) {
            float* wq = sm_w[q];
            float m = -1e30f;
            for (int j = lane; j < NB; j += 32) m = fmaxf(m, wq[j * HH + h]);
#pragma unroll
            for (int o = 16; o; o >>= 1) m = fmaxf(m, __shfl_xor_sync(0xffffffff, m, o));
            float s = 0.f;
            for (int j = lane; j < NB; j += 32) {
                float e = __expf(wq[j * HH + h] - m);
                wq[j * HH + h] = e;
                s += e;
            }
#pragma unroll
            for (int o = 16; o; o >>= 1) s += __shfl_xor_sync(0xffffffff, s, o);
            float inv = 1.0f / s;
            for (int j = lane; j < NB; j += 32) wq[j * HH + h] *= inv;
        }
    }
    __syncthreads();

    // ---- bulk copy weights to gmem ----
    {
        float4* dst = (float4*)(gw_all + i0 * NB * HH);
        const float4* src = (const float4*)sm_w;
#pragma unroll
        for (int idx = t; idx < 2 * NB * HH / 4; idx += 256) dst[idx] = src[idx];
    }
}

// ---------------- attention part 2: T + context + output + fused LN2 ---------------
__global__ __launch_bounds__(256, 3) void attn_out(
    const float* __restrict__ x, const float* __restrict__ qkv,
    const float* __restrict__ Pv, const float* __restrict__ rv1_b,
    const float* __restrict__ rv2T, const float* __restrict__ rv2_b,
    const float* __restrict__ gw_all,
    const float* __restrict__ ln2_w, const float* __restrict__ ln2_b,
    float* __restrict__ y, float* __restrict__ xn2) {
    const int i0 = blockIdx.x * 2;
    const int t = threadIdx.x;

    __shared__ __align__(16) float sm_T[2][HH * DD];   // [q][h][k], 16KB
    __shared__ float sred[4][8];

    const float* gw0 = gw_all + i0 * NB * HH;
    const float* gw1 = gw0 + NB * HH;

    // ---- Phase B: T[q][h,k], thread t owns k = t ----
    {
        float pvb = 0.5f * rv1_b[t];
        float pvq0 = Pv[i0 * DD + t] + pvb;
        float pvq1 = Pv[(i0 + 1) * DD + t] + pvb;
        u64 T0[4] = {}, T1[4] = {};
#pragma unroll 2
        for (int j = 0; j < NB; j++) {
            float pv = Pv[j * DD + t];
            float s0 = silu_h(pvq0 - pv);
            float s1 = silu_h(pvq1 - pv);
            u64 s0p = pk2(s0, s0), s1p = pk2(s1, s1);
            ulonglong2 wA0 = *(const ulonglong2*)(gw0 + j * HH);
            ulonglong2 wA1 = *(const ulonglong2*)(gw0 + j * HH + 4);
            ulonglong2 wB0 = *(const ulonglong2*)(gw1 + j * HH);
            ulonglong2 wB1 = *(const ulonglong2*)(gw1 + j * HH + 4);
            T0[0] = fma2(s0p, wA0.x, T0[0]); T0[1] = fma2(s0p, wA0.y, T0[1]);
            T0[2] = fma2(s0p, wA1.x, T0[2]); T0[3] = fma2(s0p, wA1.y, T0[3]);
            T1[0] = fma2(s1p, wB0.x, T1[0]); T1[1] = fma2(s1p, wB0.y, T1[1]);
            T1[2] = fma2(s1p, wB1.x, T1[2]); T1[3] = fma2(s1p, wB1.y, T1[3]);
        }
#pragma unroll
        for (int c = 0; c < 4; c++) {
            float2 a = up2(T0[c]);
            sm_T[0][(2 * c) * DD + t] = a.x;
            sm_T[0][(2 * c + 1) * DD + t] = a.y;
            float2 b = up2(T1[c]);
            sm_T[1][(2 * c) * DD + t] = b.x;
            sm_T[1][(2 * c + 1) * DD + t] = b.y;
        }
    }
    __syncthreads();

    // ---- output + residual + fused LN2 ----
    {
        const int d = t;
        const int h = d >> 5;
        float c1a = 0.f, c1b = 0.f;
        const float* V = qkv + 2 * DD;
#pragma unroll 8
        for (int j = 0; j < NB; j++) {
            float v = V[j * QKVD + d];
            c1a += gw0[j * HH + h] * v;
            c1b += gw1[j * HH + h] * v;
        }
        float bv = rv2_b[d];
        float c2a = bv, c2b = bv;
        const float* T0s = sm_T[0] + h * DD;
        const float* T1s = sm_T[1] + h * DD;
#pragma unroll 8
        for (int k = 0; k < DD; k++) {
            float rv = rv2T[k * DD + d];
            c2a += rv * T0s[k];
            c2b += rv * T1s[k];
        }
        float y0 = x[i0 * DD + d] + c1a + c2a;
        float y1 = x[(i0 + 1) * DD + d] + c1b + c2b;
        y[i0 * DD + d] = y0;
        y[(i0 + 1) * DD + d] = y1;

        // fused LN2 over both rows
        float s0 = y0, q0 = y0 * y0, s1 = y1, q1 = y1 * y1;
#pragma unroll
        for (int o = 16; o; o >>= 1) {
            s0 += __shfl_xor_sync(0xffffffff, s0, o);
            q0 += __shfl_xor_sync(0xffffffff, q0, o);
            s1 += __shfl_xor_sync(0xffffffff, s1, o);
            q1 += __shfl_xor_sync(0xffffffff, q1, o);
        }
        int warp = t >> 5, lane = t & 31;
        if (lane == 0) {
            sred[0][warp] = s0; sred[1][warp] = q0;
            sred[2][warp] = s1; sred[3][warp] = q1;
        }
        __syncthreads();
        float S0 = 0.f, Q0 = 0.f, S1 = 0.f, Q1 = 0.f;
#pragma unroll
        for (int k = 0; k < 8; k++) {
            S0 += sred[0][k]; Q0 += sred[1][k];
            S1 += sred[2][k]; Q1 += sred[3][k];
        }
        float m0 = S0 * (1.0f / DD), m1 = S1 * (1.0f / DD);
        float v0 = Q0 * (1.0f / DD) - m0 * m0;
        float v1 = Q1 * (1.0f / DD) - m1 * m1;
        float lw = ln2_w[d], lb = ln2_b[d];
        xn2[i0 * DD + d] = (y0 - m0) * rsqrtf(v0 + 1e-5f) * lw + lb;
        xn2[(i0 + 1) * DD + d] = (y1 - m1) * rsqrtf(v1 + 1e-5f) * lw + lb;
    }
}

// ---------------- host launcher ----------------
extern "C" void kernel_launch(void* const* d_in, const int* in_sizes, int n_in,
                              void* d_out, int out_size) {
    const float* x      = (const float*)d_in[0];
    const float* coords = (const float*)d_in[1];
    const float* ln1_w  = (const float*)d_in[2];
    const float* ln1_b  = (const float*)d_in[3];
    const float* ln2_w  = (const float*)d_in[4];
    const float* ln2_b  = (const float*)d_in[5];
    const float* qkv_w  = (const float*)d_in[6];
    const float* qkv_b  = (const float*)d_in[7];
    const float* rb1_w  = (const float*)d_in[8];
    const float* rb1_b  = (const float*)d_in[9];
    const float* rb2_w  = (const float*)d_in[10];
    const float* rb2_b  = (const float*)d_in[11];
    const float* rv1_w  = (const float*)d_in[12];
    const float* rv1_b  = (const float*)d_in[13];
    const float* rv2_w  = (const float*)d_in[14];
    const float* rv2_b  = (const float*)d_in[15];
    const float* ffn_w1 = (const float*)d_in[16];
    const float* ffn_b1 = (const float*)d_in[17];
    const float* ffn_w2 = (const float*)d_in[18];
    const float* ffn_b2 = (const float*)d_in[19];
    const float* ffn_w3 = (const float*)d_in[20];
    const float* ffn_b3 = (const float*)d_in[21];
    float* out = (float*)d_out;

    float *p_xn, *p_qkv, *p_Pb, *p_Pv, *p_rv2T, *p_w, *p_y, *p_xn2, *p_h1;
    float2* p_PKT;
    cudaGetSymbolAddress((void**)&p_xn, g_xn);
    cudaGetSymbolAddress((void**)&p_qkv, g_qkv);
    cudaGetSymbolAddress((void**)&p_PKT, g_PKT);
    cudaGetSymbolAddress((void**)&p_Pb, g_Pb);
    cudaGetSymbolAddress((void**)&p_Pv, g_Pv);
    cudaGetSymbolAddress((void**)&p_rv2T, g_rv2T);
    cudaGetSymbolAddress((void**)&p_w, g_w);
    cudaGetSymbolAddress((void**)&p_y, g_y);
    cudaGetSymbolAddress((void**)&p_xn2, g_xn2);
    cudaGetSymbolAddress((void**)&p_h1, g_h1);

    dim3 tthr(32, 8);

    // 1. LN1
    ln_kernel<<<NB, 256>>>(x, ln1_w, ln1_b, p_xn);
    // 2. QKV = xn @ qkv_w^T + qkv_b  (+ K^T side-write into PKT.x)
    gemm_t<<<dim3(QKVD / 64, NB / 32), 256>>>(p_xn, qkv_w, qkv_b, p_PKT, p_qkv,
                                              NB, QKVD, DD);
    // 3. coords projections (half-scaled: Pb, PKT.y, Pv)
    proj3_kernel<<<NB, 256>>>(coords, rb1_w, rv1_w, p_Pb, p_PKT, p_Pv);
    // 4. attention part 1: logits + softmax   (profiled slot)
    attn_logits<<<NB / 2, 256>>>(p_qkv, p_PKT, p_Pb, rb1_b, rb2_w, rb2_b, p_w);
    // 5. rv2^T
    transpose_kernel<<<dim3(DD / 32, DD / 32), tthr>>>(rv2_w, p_rv2T, DD, DD, DD, 0);
    // 6. attention part 2 + fused LN2: y, xn2
    attn_out<<<NB / 2, 256>>>(x, p_qkv, p_Pv, rv1_b, p_rv2T, rv2_b, p_w,
                              ln2_w, ln2_b, p_y, p_xn2);
    // 7. fused SwiGLU dual-GEMM
    gemm_swiglu<<<dim3((HID + 63) / 64, NB / 32), 256>>>(p_xn2, ffn_w1, ffn_b1,
                                                         ffn_w2, ffn_b2, p_h1,
                                                         NB, HID, DD);
    // 8. out = h1 @ ffn_w3^T + ffn_b3 + y   (32x32 tiles -> 128 blocks)
    gemm_t32<<<dim3(DD / 32, NB / 32), 256>>>(p_h1, ffn_w3, ffn_b3, p_y, out,
                                              NB, DD, HID);
}

// round 9
// speedup vs baseline: 1.3044x; 1.0263x over previous
#include <cuda_runtime.h>
#include <cuda_bf16.h>

// Shapes (compile-time constants)
#define NB   512           // sequence length
#define DD   256           // model dim
#define HH   8             // heads
#define HID  682           // swiglu hidden
#define QKVD 768

typedef unsigned long long u64;

// ---------------- device scratch ----------------
__device__ float g_xn[NB * DD];
__device__ float g_qkv[NB * QKVD];
__device__ float2 g_PKT[DD * NB];    // (.x = K^T[k][j], .y = 0.5*Pb^T[k][j])
__device__ float g_Pb[NB * DD];      // 0.5 * Pb
__device__ float g_Pv[NB * DD];      // 0.5 * Pv
__device__ float g_rv2T[DD * DD];    // rv2 transposed [k][d]
__device__ float g_w[NB * NB * HH];  // softmax weights [i][j*HH+h]  (8MB)
__device__ float g_y[NB * DD];
__device__ float g_xn2[NB * DD];
__device__ float g_h1[NB * HID];

// ---- packed f32x2 helpers (sm_100+) ----
__device__ __forceinline__ u64 pk2(float lo, float hi) {
    u64 r;
    asm("mov.b64 %0, {%1, %2};" : "=l"(r) : "f"(lo), "f"(hi));
    return r;
}
__device__ __forceinline__ float2 up2(u64 v) {
    float2 f;
    asm("mov.b64 {%0, %1}, %2;" : "=f"(f.x), "=f"(f.y) : "l"(v));
    return f;
}
__device__ __forceinline__ u64 fma2(u64 a, u64 b, u64 c) {
    u64 d;
    asm("fma.rn.f32x2 %0, %1, %2, %3;" : "=l"(d) : "l"(a), "l"(b), "l"(c));
    return d;
}
__device__ __forceinline__ u64 add2(u64 a, u64 b) {
    u64 d;
    asm("add.rn.f32x2 %0, %1, %2;" : "=l"(d) : "l"(a), "l"(b));
    return d;
}

// silu from the HALF-difference s = 0.5*(a-b):
// silu(a-b) = 2s*sigmoid(2s) = s*tanh(s)+s
__device__ __forceinline__ float silu_h(float s) {
    float t;
    asm("tanh.approx.f32 %0, %1;" : "=f"(t) : "f"(s));
    return fmaf(s, t, s);
}
// accurate silu for the (cold) FFN epilogue
__device__ __forceinline__ float silu_acc(float v) {
    return v / (1.0f + __expf(-v));
}

// ---------------- LayerNorm: one block per row, 256 threads ----------------
__global__ __launch_bounds__(256) void ln_kernel(const float* __restrict__ x,
                                                 const float* __restrict__ w,
                                                 const float* __restrict__ b,
                                                 float* __restrict__ out) {
    int row = blockIdx.x, t = threadIdx.x;
    float v = x[row * DD + t];
    float s = v, q = v * v;
#pragma unroll
    for (int o = 16; o; o >>= 1) {
        s += __shfl_xor_sync(0xffffffff, s, o);
        q += __shfl_xor_sync(0xffffffff, q, o);
    }
    __shared__ float ss[8], sq[8];
    int warp = t >> 5, lane = t & 31;
    if (lane == 0) { ss[warp] = s; sq[warp] = q; }
    __syncthreads();
    s = 0.f; q = 0.f;
#pragma unroll
    for (int k = 0; k < 8; k++) { s += ss[k]; q += sq[k]; }
    float mean = s * (1.0f / DD);
    float var = q * (1.0f / DD) - mean * mean;
    out[row * DD + t] = (v - mean) * rsqrtf(var + 1e-5f) * w[t] + b[t];
}

// ---------------- coords projection (all outputs HALF-scaled) ----------------
__global__ __launch_bounds__(256) void proj3_kernel(const float* __restrict__ coords,
                                                    const float* __restrict__ rb1,
                                                    const float* __restrict__ rv1,
                                                    float* __restrict__ Pb,
                                                    float2* __restrict__ PKT,
                                                    float* __restrict__ Pv) {
    int i = blockIdx.x, k = threadIdx.x;
    float c0 = coords[i * 3 + 0], c1 = coords[i * 3 + 1], c2 = coords[i * 3 + 2];
    float pb = rb1[k * 3 + 0] * c0 + rb1[k * 3 + 1] * c1 + rb1[k * 3 + 2] * c2;
    float pv = rv1[k * 3 + 0] * c0 + rv1[k * 3 + 1] * c1 + rv1[k * 3 + 2] * c2;
    Pb[i * DD + k] = 0.5f * pb;
    PKT[k * NB + i].y = 0.5f * pb;
    Pv[i * DD + k] = 0.5f * pv;
}

// ---------------- generic 32x32-tiled transpose ----------------
__global__ __launch_bounds__(256) void transpose_kernel(const float* __restrict__ in,
                                                        float* __restrict__ out,
                                                        int R, int C, int ldin, int off) {
    __shared__ float tile[32][33];
    int c0 = blockIdx.x * 32, r0 = blockIdx.y * 32;
    int tx = threadIdx.x, ty = threadIdx.y;  // 32 x 8
#pragma unroll
    for (int s = 0; s < 32; s += 8)
        tile[ty + s][tx] = in[(r0 + ty + s) * ldin + off + c0 + tx];
    __syncthreads();
#pragma unroll
    for (int s = 0; s < 32; s += 8)
        out[(c0 + ty + s) * R + r0 + tx] = tile[tx][ty + s];
}

// ---------------- GEMM: C = A @ W^T (+bias), 32x64 tile; optional K^T side-write ----
__global__ __launch_bounds__(256, 2) void gemm_t(const float* __restrict__ A,
                                                 const float* __restrict__ W,
                                                 const float* __restrict__ bias,
                                                 float2* __restrict__ PKT,  // nullable
                                                 float* __restrict__ C,
                                                 int M, int N, int K) {
    __shared__ __align__(16) u64 As[32][34];     // [k][m] duplicated
    __shared__ __align__(16) float Ws[32][68];   // [k][n]
    int tid = threadIdx.x;
    int tx = tid & 15, ty = tid >> 4;            // tx -> n (4 cols), ty -> m (2 rows)
    int row0 = blockIdx.y * 32, col0 = blockIdx.x * 64;
    u64 acc[2][2] = {};
    for (int k0 = 0; k0 < K; k0 += 32) {
#pragma unroll
        for (int l = 0; l < 4; l++) {            // A: 32x32
            int idx = l * 256 + tid;
            int m = idx >> 5, k = idx & 31;
            int gk = k0 + k, ar = row0 + m;
            float v = (ar < M && gk < K) ? A[ar * K + gk] : 0.f;
            As[k][m] = pk2(v, v);
        }
#pragma unroll
        for (int l = 0; l < 8; l++) {            // W: 64x32
            int idx = l * 256 + tid;
            int m = idx >> 5, k = idx & 31;
            int gk = k0 + k, wr = col0 + m;
            Ws[k][m] = (wr < N && gk < K) ? W[wr * K + gk] : 0.f;
        }
        __syncthreads();
#pragma unroll
        for (int kk = 0; kk < 32; kk++) {
            ulonglong2 Av = *(const ulonglong2*)&As[kk][ty * 2];
            ulonglong2 Bv = *(const ulonglong2*)&Ws[kk][tx * 4];
            acc[0][0] = fma2(Av.x, Bv.x, acc[0][0]);
            acc[0][1] = fma2(Av.x, Bv.y, acc[0][1]);
            acc[1][0] = fma2(Av.y, Bv.x, acc[1][0]);
            acc[1][1] = fma2(Av.y, Bv.y, acc[1][1]);
        }
        __syncthreads();
    }
#pragma unroll
    for (int r = 0; r < 2; r++) {
        int m = row0 + ty * 2 + r;
        if (m >= M) continue;
#pragma unroll
        for (int c2 = 0; c2 < 2; c2++) {
            float2 v = up2(acc[r][c2]);
            int n0 = col0 + tx * 4 + c2 * 2;
            if (n0 < N) {
                float o = v.x + (bias ? bias[n0] : 0.f);
                C[m * N + n0] = o;
                if (PKT && n0 >= DD && n0 < 2 * DD) PKT[(n0 - DD) * NB + m].x = o;
            }
            if (n0 + 1 < N) {
                float o = v.y + (bias ? bias[n0 + 1] : 0.f);
                C[m * N + n0 + 1] = o;
                if (PKT && n0 + 1 >= DD && n0 + 1 < 2 * DD) PKT[(n0 + 1 - DD) * NB + m].x = o;
            }
        }
    }
}

// ---------------- GEMM 32x32 tile (better grid fill for small N) ----------------
__global__ __launch_bounds__(256, 3) void gemm_t32(const float* __restrict__ A,
                                                   const float* __restrict__ W,
                                                   const float* __restrict__ bias,
                                                   const float* __restrict__ residual,
                                                   float* __restrict__ C,
                                                   int M, int N, int K) {
    __shared__ __align__(16) u64 As[32][34];     // [k][m] duplicated
    __shared__ __align__(16) float Ws[32][36];   // [k][n]
    int tid = threadIdx.x;
    int tx = tid & 7, ty = tid >> 3;             // tx -> n (4 cols), ty -> m (1 row)
    int row0 = blockIdx.y * 32, col0 = blockIdx.x * 32;
    u64 acc[2] = {};
    for (int k0 = 0; k0 < K; k0 += 32) {
#pragma unroll
        for (int l = 0; l < 4; l++) {
            int idx = l * 256 + tid;
            int m = idx >> 5, k = idx & 31;
            int gk = k0 + k;
            int ar = row0 + m, wr = col0 + m;
            float va = (ar < M && gk < K) ? A[ar * K + gk] : 0.f;
            As[k][m] = pk2(va, va);
            Ws[k][m] = (wr < N && gk < K) ? W[wr * K + gk] : 0.f;
        }
        __syncthreads();
#pragma unroll
        for (int kk = 0; kk < 32; kk++) {
            u64 Av = As[kk][ty];
            ulonglong2 Bv = *(const ulonglong2*)&Ws[kk][tx * 4];
            acc[0] = fma2(Av, Bv.x, acc[0]);
            acc[1] = fma2(Av, Bv.y, acc[1]);
        }
        __syncthreads();
    }
    int m = row0 + ty;
    if (m < M) {
#pragma unroll
        for (int c2 = 0; c2 < 2; c2++) {
            float2 v = up2(acc[c2]);
            int n0 = col0 + tx * 4 + c2 * 2;
            if (n0 < N) {
                float o = v.x;
                if (bias) o += bias[n0];
                if (residual) o += residual[m * N + n0];
                C[m * N + n0] = o;
            }
            if (n0 + 1 < N) {
                float o = v.y;
                if (bias) o += bias[n0 + 1];
                if (residual) o += residual[m * N + n0 + 1];
                C[m * N + n0 + 1] = o;
            }
        }
    }
}

// ---------------- fused SwiGLU dual-GEMM, 32x64 tile ----------------
__global__ __launch_bounds__(256, 2) void gemm_swiglu(const float* __restrict__ A,
                                                      const float* __restrict__ W1,
                                                      const float* __restrict__ b1,
                                                      const float* __restrict__ W2,
                                                      const float* __restrict__ b2,
                                                      float* __restrict__ Hout,
                                                      int M, int N, int K) {
    __shared__ __align__(16) u64 As[32][34];
    __shared__ __align__(16) float W1s[32][68];
    __shared__ __align__(16) float W2s[32][68];
    int tid = threadIdx.x;
    int tx = tid & 15, ty = tid >> 4;
    int row0 = blockIdx.y * 32, col0 = blockIdx.x * 64;
    u64 acc1[2][2] = {};
    u64 acc2[2][2] = {};
    for (int k0 = 0; k0 < K; k0 += 32) {
#pragma unroll
        for (int l = 0; l < 4; l++) {
            int idx = l * 256 + tid;
            int m = idx >> 5, k = idx & 31;
            int gk = k0 + k, ar = row0 + m;
            float v = (ar < M && gk < K) ? A[ar * K + gk] : 0.f;
            As[k][m] = pk2(v, v);
        }
#pragma unroll
        for (int l = 0; l < 8; l++) {
            int idx = l * 256 + tid;
            int m = idx >> 5, k = idx & 31;
            int gk = k0 + k, wr = col0 + m;
            W1s[k][m] = (wr < N && gk < K) ? W1[wr * K + gk] : 0.f;
            W2s[k][m] = (wr < N && gk < K) ? W2[wr * K + gk] : 0.f;
        }
        __syncthreads();
#pragma unroll
        for (int kk = 0; kk < 32; kk++) {
            ulonglong2 Av = *(const ulonglong2*)&As[kk][ty * 2];
            ulonglong2 Bv = *(const ulonglong2*)&W1s[kk][tx * 4];
            ulonglong2 Cv = *(const ulonglong2*)&W2s[kk][tx * 4];
            acc1[0][0] = fma2(Av.x, Bv.x, acc1[0][0]);
            acc1[0][1] = fma2(Av.x, Bv.y, acc1[0][1]);
            acc1[1][0] = fma2(Av.y, Bv.x, acc1[1][0]);
            acc1[1][1] = fma2(Av.y, Bv.y, acc1[1][1]);
            acc2[0][0] = fma2(Av.x, Cv.x, acc2[0][0]);
            acc2[0][1] = fma2(Av.x, Cv.y, acc2[0][1]);
            acc2[1][0] = fma2(Av.y, Cv.x, acc2[1][0]);
            acc2[1][1] = fma2(Av.y, Cv.y, acc2[1][1]);
        }
        __syncthreads();
    }
#pragma unroll
    for (int r = 0; r < 2; r++) {
        int m = row0 + ty * 2 + r;
        if (m >= M) continue;
#pragma unroll
        for (int c2 = 0; c2 < 2; c2++) {
            float2 v1 = up2(acc1[r][c2]);
            float2 v2 = up2(acc2[r][c2]);
            int n0 = col0 + tx * 4 + c2 * 2;
            if (n0 < N)
                Hout[m * N + n0] = silu_acc(v1.x + b1[n0]) * (v2.x + b2[n0]);
            if (n0 + 1 < N)
                Hout[m * N + n0 + 1] = silu_acc(v1.y + b1[n0 + 1]) * (v2.y + b2[n0 + 1]);
        }
    }
}

// ---------------- attention part 1: logits + softmax -> g_w ----------------
__global__ __launch_bounds__(256, 3) void attn_logits(
    const float* __restrict__ qkv, const float2* __restrict__ PKT,
    const float* __restrict__ Pb, const float* __restrict__ rb1_b,
    const float* __restrict__ rb2_w, const float* __restrict__ rb2_b,
    float* __restrict__ gw_all) {
    const int i0 = blockIdx.x * 2;
    const int t = threadIdx.x;

    __shared__ __align__(16) float4 sm_qpq[DD];        // (q0, hpb0, q1, hpb1)
    __shared__ __align__(16) float sm_rb2[DD * HH];    // rb2 transposed [k][h]
    __shared__ __align__(16) float sm_w[2][NB * HH];   // logits -> weights [q][j][h]

    {
        float hb = 0.5f * rb1_b[t];
        sm_qpq[t] = make_float4(qkv[i0 * QKVD + t], Pb[i0 * DD + t] + hb,
                                qkv[(i0 + 1) * QKVD + t], Pb[(i0 + 1) * DD + t] + hb);
    }
#pragma unroll
    for (int h = 0; h < HH; h++) sm_rb2[t * HH + h] = rb2_w[h * DD + t];
    __syncthreads();

    // ---- Phase A: logits for (q in {0,1}) x (j0 = t, j1 = t+256) ----
    {
        const int j0 = t, j1 = t + 256;
        u64 bias[2][2][4] = {};   // [q][jslot][head pair]
        const float sc = 0.17677669529663687f;
#pragma unroll
        for (int h = 0; h < HH; h++) {
            u64 qk[2] = {0ull, 0ull};   // packed over (j0, j1)
#pragma unroll 4
            for (int kk = 0; kk < 32; kk++) {
                int k = h * 32 + kk;
                float2 pk0 = PKT[k * NB + j0];
                float2 pk1 = PKT[k * NB + j1];
                u64 kvp = pk2(pk0.x, pk1.x);
                ulonglong2 rA = *(const ulonglong2*)(sm_rb2 + k * HH);
                ulonglong2 rB = *(const ulonglong2*)(sm_rb2 + k * HH + 4);
                float4 qq = sm_qpq[k];
#pragma unroll
                for (int q = 0; q < 2; q++) {
                    float qv = q ? qq.z : qq.x;
                    float hy = q ? qq.w : qq.y;
                    qk[q] = fma2(pk2(qv, qv), kvp, qk[q]);
                    float u0 = silu_h(hy - pk0.y);
                    float u1 = silu_h(hy - pk1.y);
                    u64 u0p = pk2(u0, u0);
                    u64 u1p = pk2(u1, u1);
                    bias[q][0][0] = fma2(u0p, rA.x, bias[q][0][0]);
                    bias[q][0][1] = fma2(u0p, rA.y, bias[q][0][1]);
                    bias[q][0][2] = fma2(u0p, rB.x, bias[q][0][2]);
                    bias[q][0][3] = fma2(u0p, rB.y, bias[q][0][3]);
                    bias[q][1][0] = fma2(u1p, rA.x, bias[q][1][0]);
                    bias[q][1][1] = fma2(u1p, rA.y, bias[q][1][1]);
                    bias[q][1][2] = fma2(u1p, rB.x, bias[q][1][2]);
                    bias[q][1][3] = fma2(u1p, rB.y, bias[q][1][3]);
                }
            }
            // fold qk*sc into bias pair c = h>>1, slot h&1
            int c = h >> 1;
#pragma unroll
            for (int q = 0; q < 2; q++) {
                float2 qv = up2(qk[q]);
                float s0 = qv.x * sc, s1 = qv.y * sc;
                u64 p0 = (h & 1) ? pk2(0.f, s0) : pk2(s0, 0.f);
                u64 p1 = (h & 1) ? pk2(0.f, s1) : pk2(s1, 0.f);
                bias[q][0][c] = add2(bias[q][0][c], p0);
                bias[q][1][c] = add2(bias[q][1][c], p1);
            }
        }
#pragma unroll
        for (int c = 0; c < 4; c++) {
            u64 bb = pk2(rb2_b[2 * c], rb2_b[2 * c + 1]);
            *(u64*)(&sm_w[0][j0 * HH + 2 * c]) = add2(bias[0][0][c], bb);
            *(u64*)(&sm_w[0][j1 * HH + 2 * c]) = add2(bias[0][1][c], bb);
            *(u64*)(&sm_w[1][j0 * HH + 2 * c]) = add2(bias[1][0][c], bb);
            *(u64*)(&sm_w[1][j1 * HH + 2 * c]) = add2(bias[1][1][c], bb);
        }
    }
    __syncthreads();

    // ---- softmax: warp h handles head h, loop over both queries ----
    {
        int h = t >> 5, lane = t & 31;
#pragma unroll
        for (int q = 0; q < 2; q++) {
            float* wq = sm_w[q];
            float m = -1e30f;
            for (int j = lane; j < NB; j += 32) m = fmaxf(m, wq[j * HH + h]);
#pragma unroll
            for (int o = 16; o; o >>= 1) m = fmaxf(m, __shfl_xor_sync(0xffffffff, m, o));
            float s = 0.f;
            for (int j = lane; j < NB; j += 32) {
                float e = __expf(wq[j * HH + h] - m);
                wq[j * HH + h] = e;
                s += e;
            }
#pragma unroll
            for (int o = 16; o; o >>= 1) s += __shfl_xor_sync(0xffffffff, s, o);
            float inv = 1.0f / s;
            for (int j = lane; j < NB; j += 32) wq[j * HH + h] *= inv;
        }
    }
    __syncthreads();

    // ---- bulk copy weights to gmem ----
    {
        float4* dst = (float4*)(gw_all + i0 * NB * HH);
        const float4* src = (const float4*)sm_w;
#pragma unroll
        for (int idx = t; idx < 2 * NB * HH / 4; idx += 256) dst[idx] = src[idx];
    }
}

// ---------------- attention part 2: T + context + output + fused LN2 ---------------
// gw staged in smem; context-1 fused into Phase-B loop
__global__ __launch_bounds__(256, 3) void attn_out(
    const float* __restrict__ x, const float* __restrict__ qkv,
    const float* __restrict__ Pv, const float* __restrict__ rv1_b,
    const float* __restrict__ rv2T, const float* __restrict__ rv2_b,
    const float* __restrict__ gw_all,
    const float* __restrict__ ln2_w, const float* __restrict__ ln2_b,
    float* __restrict__ y, float* __restrict__ xn2) {
    const int i0 = blockIdx.x * 2;
    const int t = threadIdx.x;

    __shared__ __align__(16) float sm_gw[2][NB * HH];  // staged weights, 32KB
    __shared__ __align__(16) float sm_T[2][HH * DD];   // [q][h][k], 16KB
    __shared__ float sred[4][8];

    // ---- stage softmax weights into smem (coalesced, once) ----
    {
        const float4* src = (const float4*)(gw_all + i0 * NB * HH);
        float4* dst = (float4*)sm_gw;
#pragma unroll
        for (int idx = t; idx < 2 * NB * HH / 4; idx += 256) dst[idx] = src[idx];
    }
    __syncthreads();

    const float* gw0 = sm_gw[0];
    const float* gw1 = sm_gw[1];
    const int h = t >> 5;
    float c1a = 0.f, c1b = 0.f;

    // ---- Phase B (T accumulation) + fused context-1 ----
    {
        float pvb = 0.5f * rv1_b[t];
        float pvq0 = Pv[i0 * DD + t] + pvb;
        float pvq1 = Pv[(i0 + 1) * DD + t] + pvb;
        const float* V = qkv + 2 * DD + t;
        u64 T0[4] = {}, T1[4] = {};
#pragma unroll 2
        for (int j = 0; j < NB; j++) {
            float pv = Pv[j * DD + t];
            float v = V[j * QKVD];
            float s0 = silu_h(pvq0 - pv);
            float s1 = silu_h(pvq1 - pv);
            u64 s0p = pk2(s0, s0), s1p = pk2(s1, s1);
            ulonglong2 wA0 = *(const ulonglong2*)(gw0 + j * HH);
            ulonglong2 wA1 = *(const ulonglong2*)(gw0 + j * HH + 4);
            ulonglong2 wB0 = *(const ulonglong2*)(gw1 + j * HH);
            ulonglong2 wB1 = *(const ulonglong2*)(gw1 + j * HH + 4);
            T0[0] = fma2(s0p, wA0.x, T0[0]); T0[1] = fma2(s0p, wA0.y, T0[1]);
            T0[2] = fma2(s0p, wA1.x, T0[2]); T0[3] = fma2(s0p, wA1.y, T0[3]);
            T1[0] = fma2(s1p, wB0.x, T1[0]); T1[1] = fma2(s1p, wB0.y, T1[1]);
            T1[2] = fma2(s1p, wB1.x, T1[2]); T1[3] = fma2(s1p, wB1.y, T1[3]);
            c1a = fmaf(gw0[j * HH + h], v, c1a);
            c1b = fmaf(gw1[j * HH + h], v, c1b);
        }
#pragma unroll
        for (int c = 0; c < 4; c++) {
            float2 a = up2(T0[c]);
            sm_T[0][(2 * c) * DD + t] = a.x;
            sm_T[0][(2 * c + 1) * DD + t] = a.y;
            float2 b = up2(T1[c]);
            sm_T[1][(2 * c) * DD + t] = b.x;
            sm_T[1][(2 * c + 1) * DD + t] = b.y;
        }
    }
    __syncthreads();

    // ---- context-2 + residual + fused LN2 ----
    {
        const int d = t;
        float bv = rv2_b[d];
        float c2a = bv, c2b = bv;
        const float* T0s = sm_T[0] + h * DD;
        const float* T1s = sm_T[1] + h * DD;
#pragma unroll 8
        for (int k = 0; k < DD; k++) {
            float rv = rv2T[k * DD + d];
            c2a += rv * T0s[k];
            c2b += rv * T1s[k];
        }
        float y0 = x[i0 * DD + d] + c1a + c2a;
        float y1 = x[(i0 + 1) * DD + d] + c1b + c2b;
        y[i0 * DD + d] = y0;
        y[(i0 + 1) * DD + d] = y1;

        // fused LN2 over both rows
        float s0 = y0, q0 = y0 * y0, s1 = y1, q1 = y1 * y1;
#pragma unroll
        for (int o = 16; o; o >>= 1) {
            s0 += __shfl_xor_sync(0xffffffff, s0, o);
            q0 += __shfl_xor_sync(0xffffffff, q0, o);
            s1 += __shfl_xor_sync(0xffffffff, s1, o);
            q1 += __shfl_xor_sync(0xffffffff, q1, o);
        }
        int warp = t >> 5, lane = t & 31;
        if (lane == 0) {
            sred[0][warp] = s0; sred[1][warp] = q0;
            sred[2][warp] = s1; sred[3][warp] = q1;
        }
        __syncthreads();
        float S0 = 0.f, Q0 = 0.f, S1 = 0.f, Q1 = 0.f;
#pragma unroll
        for (int k = 0; k < 8; k++) {
            S0 += sred[0][k]; Q0 += sred[1][k];
            S1 += sred[2][k]; Q1 += sred[3][k];
        }
        float m0 = S0 * (1.0f / DD), m1 = S1 * (1.0f / DD);
        float v0 = Q0 * (1.0f / DD) - m0 * m0;
        float v1 = Q1 * (1.0f / DD) - m1 * m1;
        float lw = ln2_w[d], lb = ln2_b[d];
        xn2[i0 * DD + d] = (y0 - m0) * rsqrtf(v0 + 1e-5f) * lw + lb;
        xn2[(i0 + 1) * DD + d] = (y1 - m1) * rsqrtf(v1 + 1e-5f) * lw + lb;
    }
}

// ---------------- host launcher ----------------
extern "C" void kernel_launch(void* const* d_in, const int* in_sizes, int n_in,
                              void* d_out, int out_size) {
    const float* x      = (const float*)d_in[0];
    const float* coords = (const float*)d_in[1];
    const float* ln1_w  = (const float*)d_in[2];
    const float* ln1_b  = (const float*)d_in[3];
    const float* ln2_w  = (const float*)d_in[4];
    const float* ln2_b  = (const float*)d_in[5];
    const float* qkv_w  = (const float*)d_in[6];
    const float* qkv_b  = (const float*)d_in[7];
    const float* rb1_w  = (const float*)d_in[8];
    const float* rb1_b  = (const float*)d_in[9];
    const float* rb2_w  = (const float*)d_in[10];
    const float* rb2_b  = (const float*)d_in[11];
    const float* rv1_w  = (const float*)d_in[12];
    const float* rv1_b  = (const float*)d_in[13];
    const float* rv2_w  = (const float*)d_in[14];
    const float* rv2_b  = (const float*)d_in[15];
    const float* ffn_w1 = (const float*)d_in[16];
    const float* ffn_b1 = (const float*)d_in[17];
    const float* ffn_w2 = (const float*)d_in[18];
    const float* ffn_b2 = (const float*)d_in[19];
    const float* ffn_w3 = (const float*)d_in[20];
    const float* ffn_b3 = (const float*)d_in[21];
    float* out = (float*)d_out;

    float *p_xn, *p_qkv, *p_Pb, *p_Pv, *p_rv2T, *p_w, *p_y, *p_xn2, *p_h1;
    float2* p_PKT;
    cudaGetSymbolAddress((void**)&p_xn, g_xn);
    cudaGetSymbolAddress((void**)&p_qkv, g_qkv);
    cudaGetSymbolAddress((void**)&p_PKT, g_PKT);
    cudaGetSymbolAddress((void**)&p_Pb, g_Pb);
    cudaGetSymbolAddress((void**)&p_Pv, g_Pv);
    cudaGetSymbolAddress((void**)&p_rv2T, g_rv2T);
    cudaGetSymbolAddress((void**)&p_w, g_w);
    cudaGetSymbolAddress((void**)&p_y, g_y);
    cudaGetSymbolAddress((void**)&p_xn2, g_xn2);
    cudaGetSymbolAddress((void**)&p_h1, g_h1);

    dim3 tthr(32, 8);

    // 1. LN1
    ln_kernel<<<NB, 256>>>(x, ln1_w, ln1_b, p_xn);
    // 2. QKV = xn @ qkv_w^T + qkv_b  (+ K^T side-write into PKT.x)
    gemm_t<<<dim3(QKVD / 64, NB / 32), 256>>>(p_xn, qkv_w, qkv_b, p_PKT, p_qkv,
                                              NB, QKVD, DD);
    // 3. coords projections (half-scaled: Pb, PKT.y, Pv)
    proj3_kernel<<<NB, 256>>>(coords, rb1_w, rv1_w, p_Pb, p_PKT, p_Pv);
    // 4. attention part 1: logits + softmax   (profiled slot)
    attn_logits<<<NB / 2, 256>>>(p_qkv, p_PKT, p_Pb, rb1_b, rb2_w, rb2_b, p_w);
    // 5. rv2^T
    transpose_kernel<<<dim3(DD / 32, DD / 32), tthr>>>(rv2_w, p_rv2T, DD, DD, DD, 0);
    // 6. attention part 2 + fused LN2: y, xn2
    attn_out<<<NB / 2, 256>>>(x, p_qkv, p_Pv, rv1_b, p_rv2T, rv2_b, p_w,
                              ln2_w, ln2_b, p_y, p_xn2);
    // 7. fused SwiGLU dual-GEMM
    gemm_swiglu<<<dim3((HID + 63) / 64, NB / 32), 256>>>(p_xn2, ffn_w1, ffn_b1,
                                                         ffn_w2, ffn_b2, p_h1,
                                                         NB, HID, DD);
    // 8. out = h1 @ ffn_w3^T + ffn_b3 + y   (32x32 tiles -> 128 blocks)
    gemm_t32<<<dim3(DD / 32, NB / 32), 256>>>(p_h1, ffn_w3, ffn_b3, p_y, out,
                                              NB, DD, HID);
}

// round 10
// speedup vs baseline: 1.4039x; 1.0762x over previous
#include <cuda_runtime.h>
#include <cuda_bf16.h>

// Shapes (compile-time constants)
#define NB   512           // sequence length
#define DD   256           // model dim
#define HH   8             // heads
#define HID  682           // swiglu hidden
#define QKVD 768

typedef unsigned long long u64;

// ---------------- device scratch ----------------
__device__ float g_xn[NB * DD];
__device__ float g_qkv[NB * QKVD];
__device__ float2 g_PKT[DD * NB];    // (.x = K^T[k][j], .y = 0.5*Pb^T[k][j])
__device__ float g_Pb[NB * DD];      // 0.5 * Pb
__device__ float g_Pv[NB * DD];      // 0.5 * Pv
__device__ float g_rv2T[DD * DD];    // rv2 transposed [k][d]
__device__ float g_w[NB * NB * HH];  // logits -> softmax weights [i][j*HH+h]  (8MB)
__device__ float g_Tp[NB * 2 * HH * DD];   // partial T: [(pair*2+jh)*2+q][h*DD+k] (8MB)
__device__ float g_c1p[NB * 2 * DD];       // partial c1: [(pair*2+jh)*2+q][d] (1MB)
__device__ float g_y[NB * DD];
__device__ float g_xn2[NB * DD];
__device__ float g_h1[NB * HID];

// ---- packed f32x2 helpers (sm_100+) ----
__device__ __forceinline__ u64 pk2(float lo, float hi) {
    u64 r;
    asm("mov.b64 %0, {%1, %2};" : "=l"(r) : "f"(lo), "f"(hi));
    return r;
}
__device__ __forceinline__ float2 up2(u64 v) {
    float2 f;
    asm("mov.b64 {%0, %1}, %2;" : "=f"(f.x), "=f"(f.y) : "l"(v));
    return f;
}
__device__ __forceinline__ u64 fma2(u64 a, u64 b, u64 c) {
    u64 d;
    asm("fma.rn.f32x2 %0, %1, %2, %3;" : "=l"(d) : "l"(a), "l"(b), "l"(c));
    return d;
}
__device__ __forceinline__ u64 add2(u64 a, u64 b) {
    u64 d;
    asm("add.rn.f32x2 %0, %1, %2;" : "=l"(d) : "l"(a), "l"(b));
    return d;
}

// silu from the HALF-difference s = 0.5*(a-b): silu(a-b) = s*tanh(s)+s
__device__ __forceinline__ float silu_h(float s) {
    float t;
    asm("tanh.approx.f32 %0, %1;" : "=f"(t) : "f"(s));
    return fmaf(s, t, s);
}
// accurate silu for the (cold) FFN epilogue
__device__ __forceinline__ float silu_acc(float v) {
    return v / (1.0f + __expf(-v));
}

// ---------------- LayerNorm: one block per row, 256 threads ----------------
__global__ __launch_bounds__(256) void ln_kernel(const float* __restrict__ x,
                                                 const float* __restrict__ w,
                                                 const float* __restrict__ b,
                                                 float* __restrict__ out) {
    int row = blockIdx.x, t = threadIdx.x;
    float v = x[row * DD + t];
    float s = v, q = v * v;
#pragma unroll
    for (int o = 16; o; o >>= 1) {
        s += __shfl_xor_sync(0xffffffff, s, o);
        q += __shfl_xor_sync(0xffffffff, q, o);
    }
    __shared__ float ss[8], sq[8];
    int warp = t >> 5, lane = t & 31;
    if (lane == 0) { ss[warp] = s; sq[warp] = q; }
    __syncthreads();
    s = 0.f; q = 0.f;
#pragma unroll
    for (int k = 0; k < 8; k++) { s += ss[k]; q += sq[k]; }
    float mean = s * (1.0f / DD);
    float var = q * (1.0f / DD) - mean * mean;
    out[row * DD + t] = (v - mean) * rsqrtf(var + 1e-5f) * w[t] + b[t];
}

// ---------------- coords projection (all outputs HALF-scaled) ----------------
__global__ __launch_bounds__(256) void proj3_kernel(const float* __restrict__ coords,
                                                    const float* __restrict__ rb1,
                                                    const float* __restrict__ rv1,
                                                    float* __restrict__ Pb,
                                                    float2* __restrict__ PKT,
                                                    float* __restrict__ Pv) {
    int i = blockIdx.x, k = threadIdx.x;
    float c0 = coords[i * 3 + 0], c1 = coords[i * 3 + 1], c2 = coords[i * 3 + 2];
    float pb = rb1[k * 3 + 0] * c0 + rb1[k * 3 + 1] * c1 + rb1[k * 3 + 2] * c2;
    float pv = rv1[k * 3 + 0] * c0 + rv1[k * 3 + 1] * c1 + rv1[k * 3 + 2] * c2;
    Pb[i * DD + k] = 0.5f * pb;
    PKT[k * NB + i].y = 0.5f * pb;
    Pv[i * DD + k] = 0.5f * pv;
}

// ---------------- generic 32x32-tiled transpose ----------------
__global__ __launch_bounds__(256) void transpose_kernel(const float* __restrict__ in,
                                                        float* __restrict__ out,
                                                        int R, int C, int ldin, int off) {
    __shared__ float tile[32][33];
    int c0 = blockIdx.x * 32, r0 = blockIdx.y * 32;
    int tx = threadIdx.x, ty = threadIdx.y;  // 32 x 8
#pragma unroll
    for (int s = 0; s < 32; s += 8)
        tile[ty + s][tx] = in[(r0 + ty + s) * ldin + off + c0 + tx];
    __syncthreads();
#pragma unroll
    for (int s = 0; s < 32; s += 8)
        out[(c0 + ty + s) * R + r0 + tx] = tile[tx][ty + s];
}

// ---------------- GEMM: C = A @ W^T (+bias), 32x64 tile; optional K^T side-write ----
__global__ __launch_bounds__(256, 2) void gemm_t(const float* __restrict__ A,
                                                 const float* __restrict__ W,
                                                 const float* __restrict__ bias,
                                                 float2* __restrict__ PKT,  // nullable
                                                 float* __restrict__ C,
                                                 int M, int N, int K) {
    __shared__ __align__(16) u64 As[32][34];     // [k][m] duplicated
    __shared__ __align__(16) float Ws[32][68];   // [k][n]
    int tid = threadIdx.x;
    int tx = tid & 15, ty = tid >> 4;            // tx -> n (4 cols), ty -> m (2 rows)
    int row0 = blockIdx.y * 32, col0 = blockIdx.x * 64;
    u64 acc[2][2] = {};
    for (int k0 = 0; k0 < K; k0 += 32) {
#pragma unroll
        for (int l = 0; l < 4; l++) {            // A: 32x32
            int idx = l * 256 + tid;
            int m = idx >> 5, k = idx & 31;
            int gk = k0 + k, ar = row0 + m;
            float v = (ar < M && gk < K) ? A[ar * K + gk] : 0.f;
            As[k][m] = pk2(v, v);
        }
#pragma unroll
        for (int l = 0; l < 8; l++) {            // W: 64x32
            int idx = l * 256 + tid;
            int m = idx >> 5, k = idx & 31;
            int gk = k0 + k, wr = col0 + m;
            Ws[k][m] = (wr < N && gk < K) ? W[wr * K + gk] : 0.f;
        }
        __syncthreads();
#pragma unroll
        for (int kk = 0; kk < 32; kk++) {
            ulonglong2 Av = *(const ulonglong2*)&As[kk][ty * 2];
            ulonglong2 Bv = *(const ulonglong2*)&Ws[kk][tx * 4];
            acc[0][0] = fma2(Av.x, Bv.x, acc[0][0]);
            acc[0][1] = fma2(Av.x, Bv.y, acc[0][1]);
            acc[1][0] = fma2(Av.y, Bv.x, acc[1][0]);
            acc[1][1] = fma2(Av.y, Bv.y, acc[1][1]);
        }
        __syncthreads();
    }
#pragma unroll
    for (int r = 0; r < 2; r++) {
        int m = row0 + ty * 2 + r;
        if (m >= M) continue;
#pragma unroll
        for (int c2 = 0; c2 < 2; c2++) {
            float2 v = up2(acc[r][c2]);
            int n0 = col0 + tx * 4 + c2 * 2;
            if (n0 < N) {
                float o = v.x + (bias ? bias[n0] : 0.f);
                C[m * N + n0] = o;
                if (PKT && n0 >= DD && n0 < 2 * DD) PKT[(n0 - DD) * NB + m].x = o;
            }
            if (n0 + 1 < N) {
                float o = v.y + (bias ? bias[n0 + 1] : 0.f);
                C[m * N + n0 + 1] = o;
                if (PKT && n0 + 1 >= DD && n0 + 1 < 2 * DD) PKT[(n0 + 1 - DD) * NB + m].x = o;
            }
        }
    }
}

// ---------------- GEMM 32x32 tile (better grid fill for small N) ----------------
__global__ __launch_bounds__(256, 3) void gemm_t32(const float* __restrict__ A,
                                                   const float* __restrict__ W,
                                                   const float* __restrict__ bias,
                                                   const float* __restrict__ residual,
                                                   float* __restrict__ C,
                                                   int M, int N, int K) {
    __shared__ __align__(16) u64 As[32][34];     // [k][m] duplicated
    __shared__ __align__(16) float Ws[32][36];   // [k][n]
    int tid = threadIdx.x;
    int tx = tid & 7, ty = tid >> 3;             // tx -> n (4 cols), ty -> m (1 row)
    int row0 = blockIdx.y * 32, col0 = blockIdx.x * 32;
    u64 acc[2] = {};
    for (int k0 = 0; k0 < K; k0 += 32) {
#pragma unroll
        for (int l = 0; l < 4; l++) {
            int idx = l * 256 + tid;
            int m = idx >> 5, k = idx & 31;
            int gk = k0 + k;
            int ar = row0 + m, wr = col0 + m;
            float va = (ar < M && gk < K) ? A[ar * K + gk] : 0.f;
            As[k][m] = pk2(va, va);
            Ws[k][m] = (wr < N && gk < K) ? W[wr * K + gk] : 0.f;
        }
        __syncthreads();
#pragma unroll
        for (int kk = 0; kk < 32; kk++) {
            u64 Av = As[kk][ty];
            ulonglong2 Bv = *(const ulonglong2*)&Ws[kk][tx * 4];
            acc[0] = fma2(Av, Bv.x, acc[0]);
            acc[1] = fma2(Av, Bv.y, acc[1]);
        }
        __syncthreads();
    }
    int m = row0 + ty;
    if (m < M) {
#pragma unroll
        for (int c2 = 0; c2 < 2; c2++) {
            float2 v = up2(acc[c2]);
            int n0 = col0 + tx * 4 + c2 * 2;
            if (n0 < N) {
                float o = v.x;
                if (bias) o += bias[n0];
                if (residual) o += residual[m * N + n0];
                C[m * N + n0] = o;
            }
            if (n0 + 1 < N) {
                float o = v.y;
                if (bias) o += bias[n0 + 1];
                if (residual) o += residual[m * N + n0 + 1];
                C[m * N + n0 + 1] = o;
            }
        }
    }
}

// ---------------- fused SwiGLU dual-GEMM, 32x64 tile ----------------
__global__ __launch_bounds__(256, 2) void gemm_swiglu(const float* __restrict__ A,
                                                      const float* __restrict__ W1,
                                                      const float* __restrict__ b1,
                                                      const float* __restrict__ W2,
                                                      const float* __restrict__ b2,
                                                      float* __restrict__ Hout,
                                                      int M, int N, int K) {
    __shared__ __align__(16) u64 As[32][34];
    __shared__ __align__(16) float W1s[32][68];
    __shared__ __align__(16) float W2s[32][68];
    int tid = threadIdx.x;
    int tx = tid & 15, ty = tid >> 4;
    int row0 = blockIdx.y * 32, col0 = blockIdx.x * 64;
    u64 acc1[2][2] = {};
    u64 acc2[2][2] = {};
    for (int k0 = 0; k0 < K; k0 += 32) {
#pragma unroll
        for (int l = 0; l < 4; l++) {
            int idx = l * 256 + tid;
            int m = idx >> 5, k = idx & 31;
            int gk = k0 + k, ar = row0 + m;
            float v = (ar < M && gk < K) ? A[ar * K + gk] : 0.f;
            As[k][m] = pk2(v, v);
        }
#pragma unroll
        for (int l = 0; l < 8; l++) {
            int idx = l * 256 + tid;
            int m = idx >> 5, k = idx & 31;
            int gk = k0 + k, wr = col0 + m;
            W1s[k][m] = (wr < N && gk < K) ? W1[wr * K + gk] : 0.f;
            W2s[k][m] = (wr < N && gk < K) ? W2[wr * K + gk] : 0.f;
        }
        __syncthreads();
#pragma unroll
        for (int kk = 0; kk < 32; kk++) {
            ulonglong2 Av = *(const ulonglong2*)&As[kk][ty * 2];
            ulonglong2 Bv = *(const ulonglong2*)&W1s[kk][tx * 4];
            ulonglong2 Cv = *(const ulonglong2*)&W2s[kk][tx * 4];
            acc1[0][0] = fma2(Av.x, Bv.x, acc1[0][0]);
            acc1[0][1] = fma2(Av.x, Bv.y, acc1[0][1]);
            acc1[1][0] = fma2(Av.y, Bv.x, acc1[1][0]);
            acc1[1][1] = fma2(Av.y, Bv.y, acc1[1][1]);
            acc2[0][0] = fma2(Av.x, Cv.x, acc2[0][0]);
            acc2[0][1] = fma2(Av.x, Cv.y, acc2[0][1]);
            acc2[1][0] = fma2(Av.y, Cv.x, acc2[1][0]);
            acc2[1][1] = fma2(Av.y, Cv.y, acc2[1][1]);
        }
        __syncthreads();
    }
#pragma unroll
    for (int r = 0; r < 2; r++) {
        int m = row0 + ty * 2 + r;
        if (m >= M) continue;
#pragma unroll
        for (int c2 = 0; c2 < 2; c2++) {
            float2 v1 = up2(acc1[r][c2]);
            float2 v2 = up2(acc2[r][c2]);
            int n0 = col0 + tx * 4 + c2 * 2;
            if (n0 < N)
                Hout[m * N + n0] = silu_acc(v1.x + b1[n0]) * (v2.x + b2[n0]);
            if (n0 + 1 < N)
                Hout[m * N + n0 + 1] = silu_acc(v1.y + b1[n0 + 1]) * (v2.y + b2[n0 + 1]);
        }
    }
}

// ---------------- attention 1a: raw logits, split over j halves ----------------
// grid (NB/2 pairs, 2 j-halves); thread t owns j = jbase + t, both queries.
__global__ __launch_bounds__(256, 4) void attn_logits(
    const float* __restrict__ qkv, const float2* __restrict__ PKT,
    const float* __restrict__ Pb, const float* __restrict__ rb1_b,
    const float* __restrict__ rb2_w, const float* __restrict__ rb2_b,
    float* __restrict__ gw_all) {
    const int i0 = blockIdx.x * 2;
    const int j = blockIdx.y * 256 + threadIdx.x;
    const int t = threadIdx.x;

    __shared__ __align__(16) float4 sm_qpq[DD];        // (q0, hpb0, q1, hpb1)
    __shared__ __align__(16) float sm_rb2[DD * HH];    // rb2 transposed [k][h]

    {
        float hb = 0.5f * rb1_b[t];
        sm_qpq[t] = make_float4(qkv[i0 * QKVD + t], Pb[i0 * DD + t] + hb,
                                qkv[(i0 + 1) * QKVD + t], Pb[(i0 + 1) * DD + t] + hb);
    }
#pragma unroll
    for (int h = 0; h < HH; h++) sm_rb2[t * HH + h] = rb2_w[h * DD + t];
    __syncthreads();

    u64 bias[2][4] = {};   // [q][head pair]
    const float sc = 0.17677669529663687f;
#pragma unroll
    for (int h = 0; h < HH; h++) {
        float qk0 = 0.f, qk1 = 0.f;
#pragma unroll 4
        for (int kk = 0; kk < 32; kk++) {
            int k = h * 32 + kk;
            float2 pk = PKT[k * NB + j];
            ulonglong2 rA = *(const ulonglong2*)(sm_rb2 + k * HH);
            ulonglong2 rB = *(const ulonglong2*)(sm_rb2 + k * HH + 4);
            float4 qq = sm_qpq[k];
            qk0 = fmaf(qq.x, pk.x, qk0);
            qk1 = fmaf(qq.z, pk.x, qk1);
            float u0 = silu_h(qq.y - pk.y);
            float u1 = silu_h(qq.w - pk.y);
            u64 u0p = pk2(u0, u0);
            u64 u1p = pk2(u1, u1);
            bias[0][0] = fma2(u0p, rA.x, bias[0][0]);
            bias[0][1] = fma2(u0p, rA.y, bias[0][1]);
            bias[0][2] = fma2(u0p, rB.x, bias[0][2]);
            bias[0][3] = fma2(u0p, rB.y, bias[0][3]);
            bias[1][0] = fma2(u1p, rA.x, bias[1][0]);
            bias[1][1] = fma2(u1p, rA.y, bias[1][1]);
            bias[1][2] = fma2(u1p, rB.x, bias[1][2]);
            bias[1][3] = fma2(u1p, rB.y, bias[1][3]);
        }
        // fold qk*sc into head-pair c = h>>1, lane h&1
        int c = h >> 1;
        u64 p0 = (h & 1) ? pk2(0.f, qk0 * sc) : pk2(qk0 * sc, 0.f);
        u64 p1 = (h & 1) ? pk2(0.f, qk1 * sc) : pk2(qk1 * sc, 0.f);
        bias[0][c] = add2(bias[0][c], p0);
        bias[1][c] = add2(bias[1][c], p1);
    }
    // write raw logits
    u64* w0 = (u64*)(gw_all + i0 * NB * HH + j * HH);
    u64* w1 = (u64*)(gw_all + (i0 + 1) * NB * HH + j * HH);
#pragma unroll
    for (int c = 0; c < 4; c++) {
        u64 bb = pk2(rb2_b[2 * c], rb2_b[2 * c + 1]);
        w0[c] = add2(bias[0][c], bb);
        w1[c] = add2(bias[1][c], bb);
    }
}

// ---------------- attention 1b: softmax in place over j, per (query, head) -----------
__global__ __launch_bounds__(256, 4) void softmax_kernel(float* __restrict__ gw_all) {
    const int i = blockIdx.x;
    const int t = threadIdx.x;
    __shared__ float sw[NB * 9];   // padded [j][9] for conflict-free per-head access

    float4* gw4 = (float4*)(gw_all + i * NB * HH);
    // load (coalesced) into padded smem
#pragma unroll
    for (int l = 0; l < 4; l++) {
        int idx = l * 256 + t;              // 1024 float4
        float4 v = gw4[idx];
        int jj = idx >> 1, half = (idx & 1) * 4;
        sw[jj * 9 + half + 0] = v.x;
        sw[jj * 9 + half + 1] = v.y;
        sw[jj * 9 + half + 2] = v.z;
        sw[jj * 9 + half + 3] = v.w;
    }
    __syncthreads();
    {
        int h = t >> 5, lane = t & 31;
        float m = -1e30f;
        for (int jj = lane; jj < NB; jj += 32) m = fmaxf(m, sw[jj * 9 + h]);
#pragma unroll
        for (int o = 16; o; o >>= 1) m = fmaxf(m, __shfl_xor_sync(0xffffffff, m, o));
        float s = 0.f;
        for (int jj = lane; jj < NB; jj += 32) {
            float e = __expf(sw[jj * 9 + h] - m);
            sw[jj * 9 + h] = e;
            s += e;
        }
#pragma unroll
        for (int o = 16; o; o >>= 1) s += __shfl_xor_sync(0xffffffff, s, o);
        float inv = 1.0f / s;
        for (int jj = lane; jj < NB; jj += 32) sw[jj * 9 + h] *= inv;
    }
    __syncthreads();
    // write back
#pragma unroll
    for (int l = 0; l < 4; l++) {
        int idx = l * 256 + t;
        int jj = idx >> 1, half = (idx & 1) * 4;
        float4 v;
        v.x = sw[jj * 9 + half + 0];
        v.y = sw[jj * 9 + half + 1];
        v.z = sw[jj * 9 + half + 2];
        v.w = sw[jj * 9 + half + 3];
        gw4[idx] = v;
    }
}

// ---------------- attention 2a: partial T + partial c1, split over j halves ---------
// grid (NB/2 pairs, 2 j-halves)
__global__ __launch_bounds__(256, 4) void attn_ctx(
    const float* __restrict__ qkv, const float* __restrict__ Pv,
    const float* __restrict__ rv1_b, const float* __restrict__ gw_all,
    float* __restrict__ Tp, float* __restrict__ c1p) {
    const int pair = blockIdx.x;
    const int jh = blockIdx.y;
    const int i0 = pair * 2;
    const int jbase = jh * 256;
    const int t = threadIdx.x;

    __shared__ __align__(16) float sm_gw[2][256 * HH];  // staged weights (j half), 16KB

    // stage softmax weights for this j-half (coalesced)
    {
        const float4* s0 = (const float4*)(gw_all + i0 * NB * HH + jbase * HH);
        const float4* s1 = (const float4*)(gw_all + (i0 + 1) * NB * HH + jbase * HH);
        float4* d0 = (float4*)sm_gw[0];
        float4* d1 = (float4*)sm_gw[1];
#pragma unroll
        for (int l = 0; l < 2; l++) {
            int idx = l * 256 + t;      // 512 float4 each
            d0[idx] = s0[idx];
            d1[idx] = s1[idx];
        }
    }
    __syncthreads();

    const float* gw0 = sm_gw[0];
    const float* gw1 = sm_gw[1];
    const int h = t >> 5;
    float c1a = 0.f, c1b = 0.f;

    float pvb = 0.5f * rv1_b[t];
    float pvq0 = Pv[i0 * DD + t] + pvb;
    float pvq1 = Pv[(i0 + 1) * DD + t] + pvb;
    const float* Vp = qkv + 2 * DD + t + jbase * QKVD;
    const float* Pvp = Pv + t + jbase * DD;
    u64 T0[4] = {}, T1[4] = {};
#pragma unroll 2
    for (int jj = 0; jj < 256; jj++) {
        float pv = Pvp[jj * DD];
        float v = Vp[jj * QKVD];
        float s0 = silu_h(pvq0 - pv);
        float s1 = silu_h(pvq1 - pv);
        u64 s0p = pk2(s0, s0), s1p = pk2(s1, s1);
        ulonglong2 wA0 = *(const ulonglong2*)(gw0 + jj * HH);
        ulonglong2 wA1 = *(const ulonglong2*)(gw0 + jj * HH + 4);
        ulonglong2 wB0 = *(const ulonglong2*)(gw1 + jj * HH);
        ulonglong2 wB1 = *(const ulonglong2*)(gw1 + jj * HH + 4);
        T0[0] = fma2(s0p, wA0.x, T0[0]); T0[1] = fma2(s0p, wA0.y, T0[1]);
        T0[2] = fma2(s0p, wA1.x, T0[2]); T0[3] = fma2(s0p, wA1.y, T0[3]);
        T1[0] = fma2(s1p, wB0.x, T1[0]); T1[1] = fma2(s1p, wB0.y, T1[1]);
        T1[2] = fma2(s1p, wB1.x, T1[2]); T1[3] = fma2(s1p, wB1.y, T1[3]);
        c1a = fmaf(gw0[jj * HH + h], v, c1a);
        c1b = fmaf(gw1[jj * HH + h], v, c1b);
    }
    // write partials (coalesced per h-slice)
    int b = pair * 2 + jh;
    float* T0g = Tp + (b * 2 + 0) * (HH * DD);
    float* T1g = Tp + (b * 2 + 1) * (HH * DD);
#pragma unroll
    for (int c = 0; c < 4; c++) {
        float2 a = up2(T0[c]);
        T0g[(2 * c) * DD + t] = a.x;
        T0g[(2 * c + 1) * DD + t] = a.y;
        float2 bb = up2(T1[c]);
        T1g[(2 * c) * DD + t] = bb.x;
        T1g[(2 * c + 1) * DD + t] = bb.y;
    }
    c1p[(b * 2 + 0) * DD + t] = c1a;
    c1p[(b * 2 + 1) * DD + t] = c1b;
}

// ---------------- attention 2b: combine + context2 + residual + fused LN2 -----------
// grid NB/2 (pairs)
__global__ __launch_bounds__(256, 3) void attn_fin(
    const float* __restrict__ x, const float* __restrict__ rv2T,
    const float* __restrict__ rv2_b, const float* __restrict__ Tp,
    const float* __restrict__ c1p,
    const float* __restrict__ ln2_w, const float* __restrict__ ln2_b,
    float* __restrict__ y, float* __restrict__ xn2) {
    const int pair = blockIdx.x;
    const int i0 = pair * 2;
    const int t = threadIdx.x;

    __shared__ __align__(16) float sm_T[2][HH * DD];   // combined T, 16KB
    __shared__ float sred[4][8];

    // combine T halves (coalesced float4)
    {
        const float4* A0 = (const float4*)(Tp + ((pair * 2 + 0) * 2 + 0) * (HH * DD));
        const float4* A1 = (const float4*)(Tp + ((pair * 2 + 1) * 2 + 0) * (HH * DD));
        const float4* B0 = (const float4*)(Tp + ((pair * 2 + 0) * 2 + 1) * (HH * DD));
        const float4* B1 = (const float4*)(Tp + ((pair * 2 + 1) * 2 + 1) * (HH * DD));
        float4* D0 = (float4*)sm_T[0];
        float4* D1 = (float4*)sm_T[1];
#pragma unroll
        for (int l = 0; l < 2; l++) {
            int idx = l * 256 + t;   // 512 float4 each
            float4 a0 = A0[idx], a1 = A1[idx];
            float4 b0 = B0[idx], b1 = B1[idx];
            D0[idx] = make_float4(a0.x + a1.x, a0.y + a1.y, a0.z + a1.z, a0.w + a1.w);
            D1[idx] = make_float4(b0.x + b1.x, b0.y + b1.y, b0.z + b1.z, b0.w + b1.w);
        }
    }
    __syncthreads();

    const int d = t;
    const int h = d >> 5;
    float c1a = c1p[((pair * 2 + 0) * 2 + 0) * DD + d] + c1p[((pair * 2 + 1) * 2 + 0) * DD + d];
    float c1b = c1p[((pair * 2 + 0) * 2 + 1) * DD + d] + c1p[((pair * 2 + 1) * 2 + 1) * DD + d];

    float bv = rv2_b[d];
    float c2a = bv, c2b = bv;
    const float* T0s = sm_T[0] + h * DD;
    const float* T1s = sm_T[1] + h * DD;
#pragma unroll 8
    for (int k = 0; k < DD; k++) {
        float rv = rv2T[k * DD + d];
        c2a += rv * T0s[k];
        c2b += rv * T1s[k];
    }
    float y0 = x[i0 * DD + d] + c1a + c2a;
    float y1 = x[(i0 + 1) * DD + d] + c1b + c2b;
    y[i0 * DD + d] = y0;
    y[(i0 + 1) * DD + d] = y1;

    // fused LN2 over both rows
    float s0 = y0, q0 = y0 * y0, s1 = y1, q1 = y1 * y1;
#pragma unroll
    for (int o = 16; o; o >>= 1) {
        s0 += __shfl_xor_sync(0xffffffff, s0, o);
        q0 += __shfl_xor_sync(0xffffffff, q0, o);
        s1 += __shfl_xor_sync(0xffffffff, s1, o);
        q1 += __shfl_xor_sync(0xffffffff, q1, o);
    }
    int warp = t >> 5, lane = t & 31;
    if (lane == 0) {
        sred[0][warp] = s0; sred[1][warp] = q0;
        sred[2][warp] = s1; sred[3][warp] = q1;
    }
    __syncthreads();
    float S0 = 0.f, Q0 = 0.f, S1 = 0.f, Q1 = 0.f;
#pragma unroll
    for (int k = 0; k < 8; k++) {
        S0 += sred[0][k]; Q0 += sred[1][k];
        S1 += sred[2][k]; Q1 += sred[3][k];
    }
    float m0 = S0 * (1.0f / DD), m1 = S1 * (1.0f / DD);
    float v0 = Q0 * (1.0f / DD) - m0 * m0;
    float v1 = Q1 * (1.0f / DD) - m1 * m1;
    float lw = ln2_w[d], lb = ln2_b[d];
    xn2[i0 * DD + d] = (y0 - m0) * rsqrtf(v0 + 1e-5f) * lw + lb;
    xn2[(i0 + 1) * DD + d] = (y1 - m1) * rsqrtf(v1 + 1e-5f) * lw + lb;
}

// ---------------- host launcher ----------------
extern "C" void kernel_launch(void* const* d_in, const int* in_sizes, int n_in,
                              void* d_out, int out_size) {
    const float* x      = (const float*)d_in[0];
    const float* coords = (const float*)d_in[1];
    const float* ln1_w  = (const float*)d_in[2];
    const float* ln1_b  = (const float*)d_in[3];
    const float* ln2_w  = (const float*)d_in[4];
    const float* ln2_b  = (const float*)d_in[5];
    const float* qkv_w  = (const float*)d_in[6];
    const float* qkv_b  = (const float*)d_in[7];
    const float* rb1_w  = (const float*)d_in[8];
    const float* rb1_b  = (const float*)d_in[9];
    const float* rb2_w  = (const float*)d_in[10];
    const float* rb2_b  = (const float*)d_in[11];
    const float* rv1_w  = (const float*)d_in[12];
    const float* rv1_b  = (const float*)d_in[13];
    const float* rv2_w  = (const float*)d_in[14];
    const float* rv2_b  = (const float*)d_in[15];
    const float* ffn_w1 = (const float*)d_in[16];
    const float* ffn_b1 = (const float*)d_in[17];
    const float* ffn_w2 = (const float*)d_in[18];
    const float* ffn_b2 = (const float*)d_in[19];
    const float* ffn_w3 = (const float*)d_in[20];
    const float* ffn_b3 = (const float*)d_in[21];
    float* out = (float*)d_out;

    float *p_xn, *p_qkv, *p_Pb, *p_Pv, *p_rv2T, *p_w, *p_Tp, *p_c1p, *p_y, *p_xn2, *p_h1;
    float2* p_PKT;
    cudaGetSymbolAddress((void**)&p_xn, g_xn);
    cudaGetSymbolAddress((void**)&p_qkv, g_qkv);
    cudaGetSymbolAddress((void**)&p_PKT, g_PKT);
    cudaGetSymbolAddress((void**)&p_Pb, g_Pb);
    cudaGetSymbolAddress((void**)&p_Pv, g_Pv);
    cudaGetSymbolAddress((void**)&p_rv2T, g_rv2T);
    cudaGetSymbolAddress((void**)&p_w, g_w);
    cudaGetSymbolAddress((void**)&p_Tp, g_Tp);
    cudaGetSymbolAddress((void**)&p_c1p, g_c1p);
    cudaGetSymbolAddress((void**)&p_y, g_y);
    cudaGetSymbolAddress((void**)&p_xn2, g_xn2);
    cudaGetSymbolAddress((void**)&p_h1, g_h1);

    dim3 tthr(32, 8);

    // 1. LN1
    ln_kernel<<<NB, 256>>>(x, ln1_w, ln1_b, p_xn);
    // 2. QKV = xn @ qkv_w^T + qkv_b  (+ K^T side-write into PKT.x)
    gemm_t<<<dim3(QKVD / 64, NB / 32), 256>>>(p_xn, qkv_w, qkv_b, p_PKT, p_qkv,
                                              NB, QKVD, DD);
    // 3. coords projections (half-scaled: Pb, PKT.y, Pv)
    proj3_kernel<<<NB, 256>>>(coords, rb1_w, rv1_w, p_Pb, p_PKT, p_Pv);
    // 4. attention 1a: raw logits (j-split, 512 blocks)
    attn_logits<<<dim3(NB / 2, 2), 256>>>(p_qkv, p_PKT, p_Pb, rb1_b, rb2_w, rb2_b, p_w);
    // 5. rv2^T (independent; overlaps the pipeline bubble)
    transpose_kernel<<<dim3(DD / 32, DD / 32), tthr>>>(rv2_w, p_rv2T, DD, DD, DD, 0);
    // 6. attention 1b: softmax in place
    softmax_kernel<<<NB, 256>>>(p_w);
    // 7. attention 2a: partial T + c1 (j-split, 512 blocks)
    attn_ctx<<<dim3(NB / 2, 2), 256>>>(p_qkv, p_Pv, rv1_b, p_w, p_Tp, p_c1p);
    // 8. attention 2b: combine + c2 + residual + fused LN2
    attn_fin<<<NB / 2, 256>>>(x, p_rv2T, rv2_b, p_Tp, p_c1p, ln2_w, ln2_b, p_y, p_xn2);
    // 9. fused SwiGLU dual-GEMM
    gemm_swiglu<<<dim3((HID + 63) / 64, NB / 32), 256>>>(p_xn2, ffn_w1, ffn_b1,
                                                         ffn_w2, ffn_b2, p_h1,
                                                         NB, HID, DD);
    // 10. out = h1 @ ffn_w3^T + ffn_b3 + y   (32x32 tiles -> 128 blocks)
    gemm_t32<<<dim3(DD / 32, NB / 32), 256>>>(p_h1, ffn_w3, ffn_b3, p_y, out,
                                              NB, DD, HID);
}